// round 1
// baseline (speedup 1.0000x reference)
#include <cuda_runtime.h>
#include <cstddef>

#define NROW   8192
#define NOTHER 8192
#define EDIM   128
#define DDIM   64
#define KNBR   32
#define MPATH  4

// Scratch (device globals: allocation-free rule)
__device__ float g_PS[(size_t)MPATH * NROW * DDIM];    // src @ V  + B_p   [M][N][64]
__device__ float g_PN[(size_t)MPATH * NOTHER * DDIM];  // other @ W_p      [M][N][64]
__device__ float g_H [(size_t)MPATH * NROW * EDIM];    // H                [M][N][128]
__device__ float g_part[MPATH * (NROW / 64)];          // sem partial sums
__device__ float g_beta[MPATH];

__device__ __forceinline__ float tanha(float x) {
    float y;
    asm("tanh.approx.f32 %0, %1;" : "=f"(y) : "f"(x));
    return y;
}

// ---------------------------------------------------------------------------
// Tiled GEMM: per m, C[n,d] = sum_e A[n,e] * W[m,e,d]
//   MODE 0: out[m][n][d] = C (+ bias[m][d] if bias != nullptr)
//   MODE 1: out[m*gridDim.x + bx] = sum_{rows in tile} sum_d tanh(C+bias)*Qv[m][d]
// Block: 256 threads (16x16), tile 64 rows x 64 cols, K looped in 2 chunks of 64.
// ---------------------------------------------------------------------------
template <int MODE>
__global__ void __launch_bounds__(256) gemm_k(
    const float* __restrict__ A, int aPerM,
    const float* __restrict__ W,
    const float* __restrict__ bias,
    const float* __restrict__ Qv,
    float* __restrict__ out)
{
    const int m  = blockIdx.y;
    const int n0 = blockIdx.x * 64;
    const float* Ab = A + (aPerM ? (size_t)m * NROW * EDIM : (size_t)0);
    const float* Wb = W + (size_t)m * EDIM * DDIM;

    __shared__ float As[64][65];   // [row][e], padded
    __shared__ float Ws[64][64];   // [e][d]
    __shared__ float red[256];

    const int tid = threadIdx.x;
    const int tx  = tid & 15;
    const int ty  = tid >> 4;

    float c[4][4];
#pragma unroll
    for (int i = 0; i < 4; i++)
#pragma unroll
        for (int j = 0; j < 4; j++) c[i][j] = 0.f;

    for (int e0 = 0; e0 < EDIM; e0 += 64) {
        __syncthreads();
#pragma unroll
        for (int i = 0; i < 16; i++) {
            int li = tid + i * 256;       // 0..4095
            int r  = li >> 6;
            int cl = li & 63;
            As[r][cl] = Ab[(size_t)(n0 + r) * EDIM + e0 + cl];
            Ws[r][cl] = Wb[(size_t)(e0 + r) * DDIM + cl];
        }
        __syncthreads();

#pragma unroll 16
        for (int k = 0; k < 64; k++) {
            float a0 = As[ty * 4 + 0][k];
            float a1 = As[ty * 4 + 1][k];
            float a2 = As[ty * 4 + 2][k];
            float a3 = As[ty * 4 + 3][k];
            float4 b = *(const float4*)(&Ws[k][tx * 4]);
            c[0][0] += a0 * b.x; c[0][1] += a0 * b.y; c[0][2] += a0 * b.z; c[0][3] += a0 * b.w;
            c[1][0] += a1 * b.x; c[1][1] += a1 * b.y; c[1][2] += a1 * b.z; c[1][3] += a1 * b.w;
            c[2][0] += a2 * b.x; c[2][1] += a2 * b.y; c[2][2] += a2 * b.z; c[2][3] += a2 * b.w;
            c[3][0] += a3 * b.x; c[3][1] += a3 * b.y; c[3][2] += a3 * b.z; c[3][3] += a3 * b.w;
        }
    }

    if (MODE == 0) {
        float4 bb = make_float4(0.f, 0.f, 0.f, 0.f);
        if (bias) bb = *(const float4*)(&bias[m * DDIM + tx * 4]);
#pragma unroll
        for (int i = 0; i < 4; i++) {
            float4 v = make_float4(c[i][0] + bb.x, c[i][1] + bb.y,
                                   c[i][2] + bb.z, c[i][3] + bb.w);
            *(float4*)(&out[((size_t)m * NROW + n0 + ty * 4 + i) * DDIM + tx * 4]) = v;
        }
    } else {
        float4 bb = *(const float4*)(&bias[m * DDIM + tx * 4]);
        float4 qq = *(const float4*)(&Qv[m * DDIM + tx * 4]);
        float sv = 0.f;
#pragma unroll
        for (int i = 0; i < 4; i++) {
            sv += tanha(c[i][0] + bb.x) * qq.x + tanha(c[i][1] + bb.y) * qq.y
                + tanha(c[i][2] + bb.z) * qq.z + tanha(c[i][3] + bb.w) * qq.w;
        }
        red[tid] = sv;
        __syncthreads();
#pragma unroll
        for (int s2 = 128; s2 > 0; s2 >>= 1) {
            if (tid < s2) red[tid] += red[tid + s2];
            __syncthreads();
        }
        if (tid == 0) out[m * gridDim.x + blockIdx.x] = red[0];
    }
}

// ---------------------------------------------------------------------------
// Attention + aggregation: one warp per (m, n).
//   scores[k] = sum_d tanh(PS[m,n,d] + PN[m,idx_k,d]) * X[m,d]   (B_p folded in PS)
//   softmax over full n_other axis (baseline mass for non-neighbors)
//   H[m,n,:] = src[n,:] + sum_k A_k * other[idx_k,:]
// ---------------------------------------------------------------------------
__global__ void __launch_bounds__(256) attn_k(
    const float* __restrict__ PS,
    const float* __restrict__ PN,
    const float* __restrict__ X,      // [M][64]
    const float* __restrict__ src,    // [NROW][128]
    const float* __restrict__ other,  // [NOTHER][128]
    const int*   __restrict__ nbrs,   // [M][NROW][K]
    float* __restrict__ H)
{
    const int w    = blockIdx.x * 8 + (threadIdx.x >> 5);
    const int lane = threadIdx.x & 31;
    const int m = w >> 13;
    const int n = w & (NROW - 1);
    const size_t base = (size_t)m * NROW + n;

    const float psb0 = PS[base * DDIM + lane];
    const float psb1 = PS[base * DDIM + 32 + lane];
    const float x0   = X[m * DDIM + lane];
    const float x1   = X[m * DDIM + 32 + lane];
    const int myidx  = nbrs[base * KNBR + lane];
    const float* PNm = PN + (size_t)m * NOTHER * DDIM;

    float myscore = 0.f;
#pragma unroll
    for (int k = 0; k < KNBR; k++) {
        int idx = __shfl_sync(0xffffffffu, myidx, k);
        const float* pn = PNm + (size_t)idx * DDIM;
        float t0 = tanha(psb0 + pn[lane]);
        float t1 = tanha(psb1 + pn[lane + 32]);
        float p = t0 * x0 + t1 * x1;
        p += __shfl_xor_sync(0xffffffffu, p, 16);
        p += __shfl_xor_sync(0xffffffffu, p, 8);
        p += __shfl_xor_sync(0xffffffffu, p, 4);
        p += __shfl_xor_sync(0xffffffffu, p, 2);
        p += __shfl_xor_sync(0xffffffffu, p, 1);
        if (lane == k) myscore = p;
    }

    const float baseline = (m == 0) ? -1e-9f : 1.220703125e-4f;  // 1/8192
    float mx = myscore;
    mx = fmaxf(mx, __shfl_xor_sync(0xffffffffu, mx, 16));
    mx = fmaxf(mx, __shfl_xor_sync(0xffffffffu, mx, 8));
    mx = fmaxf(mx, __shfl_xor_sync(0xffffffffu, mx, 4));
    mx = fmaxf(mx, __shfl_xor_sync(0xffffffffu, mx, 2));
    mx = fmaxf(mx, __shfl_xor_sync(0xffffffffu, mx, 1));
    mx = fmaxf(mx, baseline);

    float e = __expf(myscore - mx);
    float s = e;
    s += __shfl_xor_sync(0xffffffffu, s, 16);
    s += __shfl_xor_sync(0xffffffffu, s, 8);
    s += __shfl_xor_sync(0xffffffffu, s, 4);
    s += __shfl_xor_sync(0xffffffffu, s, 2);
    s += __shfl_xor_sync(0xffffffffu, s, 1);
    const float denom = s + (float)(NOTHER - KNBR) * __expf(baseline - mx);
    const float a = e / denom;   // lane k holds A_k

    const float4* src4 = (const float4*)src;
    const float4* oth4 = (const float4*)other;
    float4 acc = src4[(size_t)n * 32 + lane];
#pragma unroll
    for (int k = 0; k < KNBR; k++) {
        float ak = __shfl_sync(0xffffffffu, a, k);
        int idx  = __shfl_sync(0xffffffffu, myidx, k);
        float4 v = oth4[(size_t)idx * 32 + lane];
        acc.x += ak * v.x; acc.y += ak * v.y; acc.z += ak * v.z; acc.w += ak * v.w;
    }
    ((float4*)H)[base * 32 + lane] = acc;
}

// ---------------------------------------------------------------------------
// beta = softmax_m( mean_n(sem . q) )  from per-block partial sums
// ---------------------------------------------------------------------------
__global__ void beta_k(const float* __restrict__ part, float* __restrict__ beta, int nblk)
{
    const int m = threadIdx.x >> 5;
    const int lane = threadIdx.x & 31;
    float s = 0.f;
    for (int j = lane; j < nblk; j += 32) s += part[m * nblk + j];
    s += __shfl_xor_sync(0xffffffffu, s, 16);
    s += __shfl_xor_sync(0xffffffffu, s, 8);
    s += __shfl_xor_sync(0xffffffffu, s, 4);
    s += __shfl_xor_sync(0xffffffffu, s, 2);
    s += __shfl_xor_sync(0xffffffffu, s, 1);
    __shared__ float raw[MPATH];
    if (lane == 0) raw[m] = s * (1.f / (float)NROW);
    __syncthreads();
    if (threadIdx.x == 0) {
        float mx = fmaxf(fmaxf(raw[0], raw[1]), fmaxf(raw[2], raw[3]));
        float e0 = expf(raw[0] - mx), e1 = expf(raw[1] - mx);
        float e2 = expf(raw[2] - mx), e3 = expf(raw[3] - mx);
        float dn = e0 + e1 + e2 + e3;
        beta[0] = e0 / dn; beta[1] = e1 / dn; beta[2] = e2 / dn; beta[3] = e3 / dn;
    }
}

// out[n,e] = sum_m beta[m] * H[m,n,e]
__global__ void combine_k(const float* __restrict__ H, const float* __restrict__ beta,
                          float* __restrict__ out)
{
    const int i = blockIdx.x * blockDim.x + threadIdx.x;
    const int S = NROW * EDIM / 4;
    const float b0 = beta[0], b1 = beta[1], b2 = beta[2], b3 = beta[3];
    const float4* H4 = (const float4*)H;
    float4 h0 = H4[i], h1 = H4[i + S], h2 = H4[i + 2 * S], h3 = H4[i + 3 * S];
    float4 r;
    r.x = b0 * h0.x + b1 * h1.x + b2 * h2.x + b3 * h3.x;
    r.y = b0 * h0.y + b1 * h1.y + b2 * h2.y + b3 * h3.y;
    r.z = b0 * h0.z + b1 * h1.z + b2 * h2.z + b3 * h3.z;
    r.w = b0 * h0.w + b1 * h1.w + b2 * h2.w + b3 * h3.w;
    ((float4*)out)[i] = r;
}

extern "C" void kernel_launch(void* const* d_in, const int* in_sizes, int n_in,
                              void* d_out, int out_size)
{
    (void)in_sizes; (void)n_in; (void)out_size;

    const float* user    = (const float*)d_in[0];
    const float* product = (const float*)d_in[1];
    const float* V   = (const float*)d_in[2];
    const float* X   = (const float*)d_in[3];
    const float* Wp  = (const float*)d_in[4];
    const float* Bp  = (const float*)d_in[5];
    const float* Wq  = (const float*)d_in[6];
    const float* Bq  = (const float*)d_in[7];
    const float* Q   = (const float*)d_in[8];
    const int* unbrs = (const int*)d_in[9];
    const int* pnbrs = (const int*)d_in[10];
    float* out = (float*)d_out;

    float *dPS, *dPN, *dH, *dPart, *dBeta;
    cudaGetSymbolAddress((void**)&dPS,   g_PS);
    cudaGetSymbolAddress((void**)&dPN,   g_PN);
    cudaGetSymbolAddress((void**)&dH,    g_H);
    cudaGetSymbolAddress((void**)&dPart, g_part);
    cudaGetSymbolAddress((void**)&dBeta, g_beta);

    for (int p = 0; p < 2; p++) {
        const float* src   = (p == 0) ? user    : product;
        const float* other = (p == 0) ? product : out;       // phase 2 attends over user_out
        const int*   nbrs  = (p == 0) ? unbrs   : pnbrs;
        const float* Vp  = V  + (size_t)p * MPATH * EDIM * DDIM;
        const float* Xp  = X  + (size_t)p * MPATH * DDIM;
        const float* Wpp = Wp + (size_t)p * MPATH * EDIM * DDIM;
        const float* Bpp = Bp + (size_t)p * MPATH * DDIM;
        const float* Wqp = Wq + (size_t)p * MPATH * EDIM * DDIM;
        const float* Bqp = Bq + (size_t)p * MPATH * DDIM;
        const float* Qp  = Q  + (size_t)p * MPATH * DDIM;
        float* outp = out + (size_t)p * NROW * EDIM;

        dim3 gg(NROW / 64, MPATH);
        gemm_k<0><<<gg, 256>>>(src,   0, Vp,  Bpp,     nullptr, dPS);  // PS = src@V + B_p
        gemm_k<0><<<gg, 256>>>(other, 0, Wpp, nullptr, nullptr, dPN);  // PN = other@W_p
        attn_k<<<MPATH * NROW / 8, 256>>>(dPS, dPN, Xp, src, other, nbrs, dH);
        gemm_k<1><<<gg, 256>>>(dH, 1, Wqp, Bqp, Qp, dPart);            // sem partials
        beta_k<<<1, 128>>>(dPart, dBeta, NROW / 64);
        combine_k<<<NROW * EDIM / 4 / 256, 256>>>(dH, dBeta, outp);
    }
}

// round 3
// speedup vs baseline: 1.2149x; 1.2149x over previous
#include <cuda_runtime.h>
#include <mma.h>
#include <cstddef>

using namespace nvcuda;

#define NROW   8192
#define NOTHER 8192
#define EDIM   128
#define DDIM   64
#define KNBR   32
#define MPATH  4

#define LDA 136            // padded A smem stride (floats)
#define LDW 72             // padded W/C smem stride (floats)
#define SMEM_BYTES ((128 * LDA + 128 * LDW) * 4)

// Scratch (device globals: allocation-free rule)
__device__ float g_PS[(size_t)MPATH * NROW * DDIM];    // src @ V          [M][N][64]
__device__ float g_PN[(size_t)MPATH * NOTHER * DDIM];  // other @ W_p      [M][N][64]
__device__ float g_H [(size_t)MPATH * NROW * EDIM];    // H                [M][N][128]
__device__ float g_part[MPATH * 64];                   // sem partial sums
__device__ float g_beta[MPATH];

__device__ __forceinline__ float tanha(float x) {
    float y;
    asm("tanh.approx.f32 %0, %1;" : "=f"(y) : "f"(x));
    return y;
}

// ---------------------------------------------------------------------------
// Tensor-core GEMM (tf32 wmma, m16n16k8). Per (m, row-tile): C = A @ W[m].
//   Block: 256 threads (8 warps). Tile: 128 rows x 64 cols, full K=128 in smem.
//   MODE 0: out[z][m][n][d] = C   (no bias; z selects {A0,W0,out0} / {A1,W1,out1})
//   MODE 1: out0[m*gridDim.x+bx] = sum_rows sum_d tanh(C + bias[m][d]) * Qv[m][d]
// ---------------------------------------------------------------------------
template <int MODE>
__global__ void __launch_bounds__(256) gemm_tc(
    const float* __restrict__ A0, const float* __restrict__ W0, float* __restrict__ out0,
    const float* __restrict__ A1, const float* __restrict__ W1, float* __restrict__ out1,
    const float* __restrict__ bias, const float* __restrict__ Qv, int aPerM)
{
    extern __shared__ float sm[];
    float* As = sm;                 // [128][LDA]
    float* Ws = sm + 128 * LDA;     // [128][LDW], reused as C in MODE 1

    const int m  = blockIdx.y;
    const int n0 = blockIdx.x * 128;
    const int tid = threadIdx.x;
    const int wid = tid >> 5;

    const float* A = (MODE == 0 && blockIdx.z == 1) ? A1 : A0;
    const float* W = ((MODE == 0 && blockIdx.z == 1) ? W1 : W0) + (size_t)m * EDIM * DDIM;
    float* out = (MODE == 0 && blockIdx.z == 1) ? out1 : out0;
    if (aPerM) A += (size_t)m * NROW * EDIM;

    __shared__ float sB[DDIM], sQ[DDIM], red[8];
    if (MODE == 1 && tid < DDIM) {
        sB[tid] = bias[m * DDIM + tid];
        sQ[tid] = Qv[m * DDIM + tid];
    }

    // Load A tile (128x128) -> smem, converting to tf32-rounded floats
#pragma unroll
    for (int i = 0; i < 16; i++) {
        int li = tid + i * 256;            // float4 index, 4096 total
        int r = li >> 5, c4 = (li & 31) << 2;
        float4 v = *(const float4*)(A + (size_t)(n0 + r) * EDIM + c4);
        float* d = As + r * LDA + c4;
        d[0] = wmma::__float_to_tf32(v.x);
        d[1] = wmma::__float_to_tf32(v.y);
        d[2] = wmma::__float_to_tf32(v.z);
        d[3] = wmma::__float_to_tf32(v.w);
    }
    // Load W (128x64) -> smem
#pragma unroll
    for (int i = 0; i < 8; i++) {
        int li = tid + i * 256;            // float4 index, 2048 total
        int r = li >> 4, c4 = (li & 15) << 2;
        float4 v = *(const float4*)(W + (size_t)r * DDIM + c4);
        float* d = Ws + r * LDW + c4;
        d[0] = wmma::__float_to_tf32(v.x);
        d[1] = wmma::__float_to_tf32(v.y);
        d[2] = wmma::__float_to_tf32(v.z);
        d[3] = wmma::__float_to_tf32(v.w);
    }
    __syncthreads();

    wmma::fragment<wmma::accumulator, 16, 16, 8, float> acc[4];
#pragma unroll
    for (int t = 0; t < 4; t++) wmma::fill_fragment(acc[t], 0.f);

    const int row0 = wid * 16;
#pragma unroll
    for (int k = 0; k < 16; k++) {
        wmma::fragment<wmma::matrix_a, 16, 16, 8, wmma::precision::tf32, wmma::row_major> af;
        wmma::load_matrix_sync(af, As + row0 * LDA + k * 8, LDA);
#pragma unroll
        for (int t = 0; t < 4; t++) {
            wmma::fragment<wmma::matrix_b, 16, 16, 8, wmma::precision::tf32, wmma::row_major> bf;
            wmma::load_matrix_sync(bf, Ws + (k * 8) * LDW + t * 16, LDW);
            wmma::mma_sync(acc[t], af, bf, acc[t]);
        }
    }

    if (MODE == 0) {
#pragma unroll
        for (int t = 0; t < 4; t++) {
            wmma::store_matrix_sync(
                out + ((size_t)m * NROW + n0 + row0) * DDIM + t * 16,
                acc[t], DDIM, wmma::mem_row_major);
        }
    } else {
        __syncthreads();   // all warps done reading Ws
#pragma unroll
        for (int t = 0; t < 4; t++)
            wmma::store_matrix_sync(Ws + row0 * LDW + t * 16, acc[t], LDW, wmma::mem_row_major);
        __syncthreads();

        float sv = 0.f;
#pragma unroll 4
        for (int li = tid; li < 128 * 64; li += 256) {
            int r = li >> 6, d = li & 63;
            sv += tanha(Ws[r * LDW + d] + sB[d]) * sQ[d];
        }
        sv += __shfl_xor_sync(0xffffffffu, sv, 16);
        sv += __shfl_xor_sync(0xffffffffu, sv, 8);
        sv += __shfl_xor_sync(0xffffffffu, sv, 4);
        sv += __shfl_xor_sync(0xffffffffu, sv, 2);
        sv += __shfl_xor_sync(0xffffffffu, sv, 1);
        if ((tid & 31) == 0) red[wid] = sv;
        __syncthreads();
        if (tid == 0) {
            float s = 0.f;
#pragma unroll
            for (int i = 0; i < 8; i++) s += red[i];
            out0[m * gridDim.x + blockIdx.x] = s;
        }
    }
}

// ---------------------------------------------------------------------------
// Attention + aggregation: one warp per (m, n).
//   scores[k] = sum_d tanh(PS[m,n,d] + Bp[m,d] + PN[m,idx_k,d]) * X[m,d]
//   softmax over full n_other axis (baseline mass for non-neighbors)
//   H[m,n,:] = src[n,:] + sum_k A_k * other[idx_k,:]
// ---------------------------------------------------------------------------
__global__ void __launch_bounds__(256) attn_k(
    const float* __restrict__ PS,
    const float* __restrict__ PN,
    const float* __restrict__ Bp,     // [M][64]
    const float* __restrict__ X,      // [M][64]
    const float* __restrict__ src,    // [NROW][128]
    const float* __restrict__ other,  // [NOTHER][128]
    const int*   __restrict__ nbrs,   // [M][NROW][K]
    float* __restrict__ H)
{
    const int w    = blockIdx.x * 8 + (threadIdx.x >> 5);
    const int lane = threadIdx.x & 31;
    const int m = w >> 13;
    const int n = w & (NROW - 1);
    const size_t base = (size_t)m * NROW + n;

    const float psb0 = PS[base * DDIM + lane]      + Bp[m * DDIM + lane];
    const float psb1 = PS[base * DDIM + 32 + lane] + Bp[m * DDIM + 32 + lane];
    const float x0   = X[m * DDIM + lane];
    const float x1   = X[m * DDIM + 32 + lane];
    const int myidx  = nbrs[base * KNBR + lane];
    const float* PNm = PN + (size_t)m * NOTHER * DDIM;

    float myscore = 0.f;
#pragma unroll
    for (int k = 0; k < KNBR; k++) {
        int idx = __shfl_sync(0xffffffffu, myidx, k);
        const float* pn = PNm + (size_t)idx * DDIM;
        float t0 = tanha(psb0 + pn[lane]);
        float t1 = tanha(psb1 + pn[lane + 32]);
        float p = t0 * x0 + t1 * x1;
        p += __shfl_xor_sync(0xffffffffu, p, 16);
        p += __shfl_xor_sync(0xffffffffu, p, 8);
        p += __shfl_xor_sync(0xffffffffu, p, 4);
        p += __shfl_xor_sync(0xffffffffu, p, 2);
        p += __shfl_xor_sync(0xffffffffu, p, 1);
        if (lane == k) myscore = p;
    }

    const float baseline = (m == 0) ? -1e-9f : 1.220703125e-4f;  // 1/8192
    float mx = myscore;
    mx = fmaxf(mx, __shfl_xor_sync(0xffffffffu, mx, 16));
    mx = fmaxf(mx, __shfl_xor_sync(0xffffffffu, mx, 8));
    mx = fmaxf(mx, __shfl_xor_sync(0xffffffffu, mx, 4));
    mx = fmaxf(mx, __shfl_xor_sync(0xffffffffu, mx, 2));
    mx = fmaxf(mx, __shfl_xor_sync(0xffffffffu, mx, 1));
    mx = fmaxf(mx, baseline);

    float e = __expf(myscore - mx);
    float s = e;
    s += __shfl_xor_sync(0xffffffffu, s, 16);
    s += __shfl_xor_sync(0xffffffffu, s, 8);
    s += __shfl_xor_sync(0xffffffffu, s, 4);
    s += __shfl_xor_sync(0xffffffffu, s, 2);
    s += __shfl_xor_sync(0xffffffffu, s, 1);
    const float denom = s + (float)(NOTHER - KNBR) * __expf(baseline - mx);
    const float a = e / denom;   // lane k holds A_k

    const float4* src4 = (const float4*)src;
    const float4* oth4 = (const float4*)other;
    float4 acc = src4[(size_t)n * 32 + lane];
#pragma unroll
    for (int k = 0; k < KNBR; k++) {
        float ak = __shfl_sync(0xffffffffu, a, k);
        int idx  = __shfl_sync(0xffffffffu, myidx, k);
        float4 v = oth4[(size_t)idx * 32 + lane];
        acc.x += ak * v.x; acc.y += ak * v.y; acc.z += ak * v.z; acc.w += ak * v.w;
    }
    ((float4*)H)[base * 32 + lane] = acc;
}

// ---------------------------------------------------------------------------
// beta = softmax_m( mean_n(sem . q) )  from per-block partial sums
// ---------------------------------------------------------------------------
__global__ void beta_k(const float* __restrict__ part, float* __restrict__ beta, int nblk)
{
    const int m = threadIdx.x >> 5;
    const int lane = threadIdx.x & 31;
    float s = 0.f;
    for (int j = lane; j < nblk; j += 32) s += part[m * nblk + j];
    s += __shfl_xor_sync(0xffffffffu, s, 16);
    s += __shfl_xor_sync(0xffffffffu, s, 8);
    s += __shfl_xor_sync(0xffffffffu, s, 4);
    s += __shfl_xor_sync(0xffffffffu, s, 2);
    s += __shfl_xor_sync(0xffffffffu, s, 1);
    __shared__ float raw[MPATH];
    if (lane == 0) raw[m] = s * (1.f / (float)NROW);
    __syncthreads();
    if (threadIdx.x == 0) {
        float mx = fmaxf(fmaxf(raw[0], raw[1]), fmaxf(raw[2], raw[3]));
        float e0 = expf(raw[0] - mx), e1 = expf(raw[1] - mx);
        float e2 = expf(raw[2] - mx), e3 = expf(raw[3] - mx);
        float dn = e0 + e1 + e2 + e3;
        beta[0] = e0 / dn; beta[1] = e1 / dn; beta[2] = e2 / dn; beta[3] = e3 / dn;
    }
}

// out[n,e] = sum_m beta[m] * H[m,n,e]
__global__ void combine_k(const float* __restrict__ H, const float* __restrict__ beta,
                          float* __restrict__ out)
{
    const int i = blockIdx.x * blockDim.x + threadIdx.x;
    const int S = NROW * EDIM / 4;
    const float b0 = beta[0], b1 = beta[1], b2 = beta[2], b3 = beta[3];
    const float4* H4 = (const float4*)H;
    float4 h0 = H4[i], h1 = H4[i + S], h2 = H4[i + 2 * S], h3 = H4[i + 3 * S];
    float4 r;
    r.x = b0 * h0.x + b1 * h1.x + b2 * h2.x + b3 * h3.x;
    r.y = b0 * h0.y + b1 * h1.y + b2 * h2.y + b3 * h3.y;
    r.z = b0 * h0.z + b1 * h1.z + b2 * h2.z + b3 * h3.z;
    r.w = b0 * h0.w + b1 * h1.w + b2 * h2.w + b3 * h3.w;
    ((float4*)out)[i] = r;
}

extern "C" void kernel_launch(void* const* d_in, const int* in_sizes, int n_in,
                              void* d_out, int out_size)
{
    (void)in_sizes; (void)n_in; (void)out_size;

    const float* user    = (const float*)d_in[0];
    const float* product = (const float*)d_in[1];
    const float* V   = (const float*)d_in[2];
    const float* X   = (const float*)d_in[3];
    const float* Wp  = (const float*)d_in[4];
    const float* Bp  = (const float*)d_in[5];
    const float* Wq  = (const float*)d_in[6];
    const float* Bq  = (const float*)d_in[7];
    const float* Q   = (const float*)d_in[8];
    const int* unbrs = (const int*)d_in[9];
    const int* pnbrs = (const int*)d_in[10];
    float* out = (float*)d_out;

    float *dPS, *dPN, *dH, *dPart, *dBeta;
    cudaGetSymbolAddress((void**)&dPS,   g_PS);
    cudaGetSymbolAddress((void**)&dPN,   g_PN);
    cudaGetSymbolAddress((void**)&dH,    g_H);
    cudaGetSymbolAddress((void**)&dPart, g_part);
    cudaGetSymbolAddress((void**)&dBeta, g_beta);

    cudaFuncSetAttribute(gemm_tc<0>, cudaFuncAttributeMaxDynamicSharedMemorySize, SMEM_BYTES);
    cudaFuncSetAttribute(gemm_tc<1>, cudaFuncAttributeMaxDynamicSharedMemorySize, SMEM_BYTES);

    for (int p = 0; p < 2; p++) {
        const float* src   = (p == 0) ? user    : product;
        const float* other = (p == 0) ? product : out;       // phase 2 attends over user_out
        const int*   nbrs  = (p == 0) ? unbrs   : pnbrs;
        const float* Vp  = V  + (size_t)p * MPATH * EDIM * DDIM;
        const float* Xp  = X  + (size_t)p * MPATH * DDIM;
        const float* Wpp = Wp + (size_t)p * MPATH * EDIM * DDIM;
        const float* Bpp = Bp + (size_t)p * MPATH * DDIM;
        const float* Wqp = Wq + (size_t)p * MPATH * EDIM * DDIM;
        const float* Bqp = Bq + (size_t)p * MPATH * DDIM;
        const float* Qp  = Q  + (size_t)p * MPATH * DDIM;
        float* outp = out + (size_t)p * NROW * EDIM;

        // PS = src@V and PN = other@W_p in ONE launch (z selects)
        gemm_tc<0><<<dim3(NROW / 128, MPATH, 2), 256, SMEM_BYTES>>>(
            src, Vp, dPS, other, Wpp, dPN, nullptr, nullptr, 0);
        attn_k<<<MPATH * NROW / 8, 256>>>(dPS, dPN, Bpp, Xp, src, other, nbrs, dH);
        gemm_tc<1><<<dim3(NROW / 128, MPATH, 1), 256, SMEM_BYTES>>>(
            dH, Wqp, dPart, nullptr, nullptr, nullptr, Bqp, Qp, 1);
        beta_k<<<1, 128>>>(dPart, dBeta, NROW / 128);
        combine_k<<<NROW * EDIM / 4 / 256, 256>>>(dH, dBeta, outp);
    }
}

// round 4
// speedup vs baseline: 1.3283x; 1.0933x over previous
#include <cuda_runtime.h>
#include <cuda_bf16.h>
#include <mma.h>
#include <cstddef>

using namespace nvcuda;

#define NROW   8192
#define NOTHER 8192
#define EDIM   128
#define DDIM   64
#define KNBR   32
#define MPATH  4

#define LDA 136            // padded A smem stride (floats)
#define LDW 72             // padded W/C smem stride (floats)
#define SMEM_BYTES ((128 * LDA + 128 * LDW) * 4)

// Scratch (device globals: allocation-free rule)
__device__ float g_PS[(size_t)MPATH * NROW * DDIM];              // src @ V        (fp32)
__device__ __nv_bfloat16 g_PNh[(size_t)MPATH * NOTHER * DDIM];   // other @ W_p    (bf16)
__device__ __nv_bfloat16 g_otherh[(size_t)NOTHER * EDIM];        // bf16 shadow of gather target
__device__ float g_H [(size_t)MPATH * NROW * EDIM];              // H              (fp32)
__device__ float g_part[MPATH * 64];                             // sem partial sums

__device__ __forceinline__ float tanha(float x) {
    float y;
    asm("tanh.approx.f32 %0, %1;" : "=f"(y) : "f"(x));
    return y;
}

// ---------------------------------------------------------------------------
// Tensor-core GEMM (tf32 wmma, m16n16k8). Per (m, row-tile): C = A @ W[m].
//   Block: 256 threads (8 warps). Tile: 128 rows x 64 cols, full K=128 in smem.
//   MODE 0, z=0: outF[m][n][d] = C            (fp32, PS path)
//   MODE 0, z=1: outH[m][n][d] = bf16(C)      (bf16, PN path; A1/W1 operands)
//   MODE 1:      outF[m*gridDim.x+bx] = sum_rows sum_d tanh(C+bias[m][d])*Qv[m][d]
// ---------------------------------------------------------------------------
template <int MODE>
__global__ void __launch_bounds__(256) gemm_tc(
    const float* __restrict__ A0, const float* __restrict__ W0, float* __restrict__ outF,
    const float* __restrict__ A1, const float* __restrict__ W1, __nv_bfloat16* __restrict__ outH,
    const float* __restrict__ bias, const float* __restrict__ Qv, int aPerM)
{
    extern __shared__ float sm[];
    float* As = sm;                 // [128][LDA]
    float* Ws = sm + 128 * LDA;     // [128][LDW], reused as C staging

    const int m  = blockIdx.y;
    const int n0 = blockIdx.x * 128;
    const int tid = threadIdx.x;
    const int wid = tid >> 5;
    const int z = (MODE == 0) ? blockIdx.z : 0;

    const float* A = (z == 1) ? A1 : A0;
    const float* W = ((z == 1) ? W1 : W0) + (size_t)m * EDIM * DDIM;
    if (aPerM) A += (size_t)m * NROW * EDIM;

    __shared__ float sB[DDIM], sQ[DDIM], red[8];
    if (MODE == 1 && tid < DDIM) {
        sB[tid] = bias[m * DDIM + tid];
        sQ[tid] = Qv[m * DDIM + tid];
    }

    // Load A tile (128x128) -> smem (tf32-rounded)
#pragma unroll
    for (int i = 0; i < 16; i++) {
        int li = tid + i * 256;            // float4 index, 4096 total
        int r = li >> 5, c4 = (li & 31) << 2;
        float4 v = *(const float4*)(A + (size_t)(n0 + r) * EDIM + c4);
        float* d = As + r * LDA + c4;
        d[0] = wmma::__float_to_tf32(v.x);
        d[1] = wmma::__float_to_tf32(v.y);
        d[2] = wmma::__float_to_tf32(v.z);
        d[3] = wmma::__float_to_tf32(v.w);
    }
    // Load W (128x64) -> smem
#pragma unroll
    for (int i = 0; i < 8; i++) {
        int li = tid + i * 256;            // float4 index, 2048 total
        int r = li >> 4, c4 = (li & 15) << 2;
        float4 v = *(const float4*)(W + (size_t)r * DDIM + c4);
        float* d = Ws + r * LDW + c4;
        d[0] = wmma::__float_to_tf32(v.x);
        d[1] = wmma::__float_to_tf32(v.y);
        d[2] = wmma::__float_to_tf32(v.z);
        d[3] = wmma::__float_to_tf32(v.w);
    }
    __syncthreads();

    wmma::fragment<wmma::accumulator, 16, 16, 8, float> acc[4];
#pragma unroll
    for (int t = 0; t < 4; t++) wmma::fill_fragment(acc[t], 0.f);

    const int row0 = wid * 16;
#pragma unroll
    for (int k = 0; k < 16; k++) {
        wmma::fragment<wmma::matrix_a, 16, 16, 8, wmma::precision::tf32, wmma::row_major> af;
        wmma::load_matrix_sync(af, As + row0 * LDA + k * 8, LDA);
#pragma unroll
        for (int t = 0; t < 4; t++) {
            wmma::fragment<wmma::matrix_b, 16, 16, 8, wmma::precision::tf32, wmma::row_major> bf;
            wmma::load_matrix_sync(bf, Ws + (k * 8) * LDW + t * 16, LDW);
            wmma::mma_sync(acc[t], af, bf, acc[t]);
        }
    }

    if (MODE == 0 && z == 0) {
#pragma unroll
        for (int t = 0; t < 4; t++) {
            wmma::store_matrix_sync(
                outF + ((size_t)m * NROW + n0 + row0) * DDIM + t * 16,
                acc[t], DDIM, wmma::mem_row_major);
        }
    } else if (MODE == 0) {
        // bf16 output: stage C in smem (Ws free now), convert
        __syncthreads();
#pragma unroll
        for (int t = 0; t < 4; t++)
            wmma::store_matrix_sync(Ws + row0 * LDW + t * 16, acc[t], LDW, wmma::mem_row_major);
        __syncthreads();
#pragma unroll
        for (int i = 0; i < 16; i++) {
            int li = tid + i * 256;          // pair index over 4096 pairs
            int r = li >> 5, c2 = (li & 31) << 1;
            __nv_bfloat162 b = __floats2bfloat162_rn(Ws[r * LDW + c2], Ws[r * LDW + c2 + 1]);
            *(__nv_bfloat162*)(outH + ((size_t)m * NROW + n0 + r) * DDIM + c2) = b;
        }
    } else {
        __syncthreads();
#pragma unroll
        for (int t = 0; t < 4; t++)
            wmma::store_matrix_sync(Ws + row0 * LDW + t * 16, acc[t], LDW, wmma::mem_row_major);
        __syncthreads();

        float sv = 0.f;
#pragma unroll 4
        for (int li = tid; li < 128 * 64; li += 256) {
            int r = li >> 6, d = li & 63;
            sv += tanha(Ws[r * LDW + d] + sB[d]) * sQ[d];
        }
        sv += __shfl_xor_sync(0xffffffffu, sv, 16);
        sv += __shfl_xor_sync(0xffffffffu, sv, 8);
        sv += __shfl_xor_sync(0xffffffffu, sv, 4);
        sv += __shfl_xor_sync(0xffffffffu, sv, 2);
        sv += __shfl_xor_sync(0xffffffffu, sv, 1);
        if ((tid & 31) == 0) red[wid] = sv;
        __syncthreads();
        if (tid == 0) {
            float s = 0.f;
#pragma unroll
            for (int i = 0; i < 8; i++) s += red[i];
            outF[m * gridDim.x + blockIdx.x] = s;
        }
    }
}

// ---------------------------------------------------------------------------
// Attention + aggregation: one warp per (m, n). bf16 gathers.
//   Lane owns dims (2l, 2l+1) for scores, dims (4l..4l+3) for aggregation.
// ---------------------------------------------------------------------------
__global__ void __launch_bounds__(256) attn_k(
    const float* __restrict__ PS,
    const __nv_bfloat16* __restrict__ PNh,
    const float* __restrict__ Bp,     // [M][64]
    const float* __restrict__ X,      // [M][64]
    const float* __restrict__ src,    // [NROW][128]
    const __nv_bfloat16* __restrict__ otherh,  // [NOTHER][128] bf16
    const int*   __restrict__ nbrs,   // [M][NROW][K]
    float* __restrict__ H)
{
    const int w    = blockIdx.x * 8 + (threadIdx.x >> 5);
    const int lane = threadIdx.x & 31;
    const int m = w >> 13;
    const int n = w & (NROW - 1);
    const size_t base = (size_t)m * NROW + n;

    float2 psv = *(const float2*)(PS + base * DDIM + 2 * lane);
    float2 bpv = *(const float2*)(Bp + m * DDIM + 2 * lane);
    const float ps0 = psv.x + bpv.x;
    const float ps1 = psv.y + bpv.y;
    const float2 xv = *(const float2*)(X + m * DDIM + 2 * lane);
    const int myidx  = nbrs[base * KNBR + lane];
    const __nv_bfloat16* PNm = PNh + (size_t)m * NOTHER * DDIM;

    float myscore = 0.f;
#pragma unroll
    for (int k = 0; k < KNBR; k++) {
        int idx = __shfl_sync(0xffffffffu, myidx, k);
        __nv_bfloat162 pn = *(const __nv_bfloat162*)(PNm + (size_t)idx * DDIM + 2 * lane);
        float t0 = tanha(ps0 + __low2float(pn));
        float t1 = tanha(ps1 + __high2float(pn));
        float p = t0 * xv.x + t1 * xv.y;
        p += __shfl_xor_sync(0xffffffffu, p, 16);
        p += __shfl_xor_sync(0xffffffffu, p, 8);
        p += __shfl_xor_sync(0xffffffffu, p, 4);
        p += __shfl_xor_sync(0xffffffffu, p, 2);
        p += __shfl_xor_sync(0xffffffffu, p, 1);
        if (lane == k) myscore = p;
    }

    const float baseline = (m == 0) ? -1e-9f : 1.220703125e-4f;  // 1/8192
    float mx = myscore;
    mx = fmaxf(mx, __shfl_xor_sync(0xffffffffu, mx, 16));
    mx = fmaxf(mx, __shfl_xor_sync(0xffffffffu, mx, 8));
    mx = fmaxf(mx, __shfl_xor_sync(0xffffffffu, mx, 4));
    mx = fmaxf(mx, __shfl_xor_sync(0xffffffffu, mx, 2));
    mx = fmaxf(mx, __shfl_xor_sync(0xffffffffu, mx, 1));
    mx = fmaxf(mx, baseline);

    float e = __expf(myscore - mx);
    float s = e;
    s += __shfl_xor_sync(0xffffffffu, s, 16);
    s += __shfl_xor_sync(0xffffffffu, s, 8);
    s += __shfl_xor_sync(0xffffffffu, s, 4);
    s += __shfl_xor_sync(0xffffffffu, s, 2);
    s += __shfl_xor_sync(0xffffffffu, s, 1);
    const float denom = s + (float)(NOTHER - KNBR) * __expf(baseline - mx);
    const float a = e / denom;   // lane k holds A_k

    const float4* src4 = (const float4*)src;
    float4 acc = src4[(size_t)n * 32 + lane];
#pragma unroll
    for (int k = 0; k < KNBR; k++) {
        float ak = __shfl_sync(0xffffffffu, a, k);
        int idx  = __shfl_sync(0xffffffffu, myidx, k);
        uint2 u = *(const uint2*)(otherh + (size_t)idx * EDIM + lane * 4);
        __nv_bfloat162 v01 = *reinterpret_cast<__nv_bfloat162*>(&u.x);
        __nv_bfloat162 v23 = *reinterpret_cast<__nv_bfloat162*>(&u.y);
        acc.x += ak * __low2float(v01);
        acc.y += ak * __high2float(v01);
        acc.z += ak * __low2float(v23);
        acc.w += ak * __high2float(v23);
    }
    ((float4*)H)[base * 32 + lane] = acc;
}

// ---------------------------------------------------------------------------
// combine: beta = softmax_m(mean partials), out[n,e] = sum_m beta[m]*H[m,n,e].
// Optionally writes a bf16 shadow of out (for next phase's gathers).
// ---------------------------------------------------------------------------
__global__ void __launch_bounds__(256) combine_k(
    const float* __restrict__ H, const float* __restrict__ part, int nblk,
    float* __restrict__ out, __nv_bfloat16* __restrict__ outh)
{
    __shared__ float sp[256];
    __shared__ float sb[MPATH];
    const int tid = threadIdx.x;
    if (tid < MPATH * 64) sp[tid] = part[tid];
    __syncthreads();
    if (tid == 0) {
        float raw[MPATH];
#pragma unroll
        for (int mm = 0; mm < MPATH; mm++) {
            float s = 0.f;
            for (int j = 0; j < nblk; j++) s += sp[mm * nblk + j];
            raw[mm] = s * (1.f / (float)NROW);
        }
        float mx = fmaxf(fmaxf(raw[0], raw[1]), fmaxf(raw[2], raw[3]));
        float e0 = expf(raw[0] - mx), e1 = expf(raw[1] - mx);
        float e2 = expf(raw[2] - mx), e3 = expf(raw[3] - mx);
        float dn = e0 + e1 + e2 + e3;
        sb[0] = e0 / dn; sb[1] = e1 / dn; sb[2] = e2 / dn; sb[3] = e3 / dn;
    }
    __syncthreads();

    const int i = blockIdx.x * 256 + tid;
    const int S = NROW * EDIM / 4;
    const float b0 = sb[0], b1 = sb[1], b2 = sb[2], b3 = sb[3];
    const float4* H4 = (const float4*)H;
    float4 h0 = H4[i], h1 = H4[i + S], h2 = H4[i + 2 * S], h3 = H4[i + 3 * S];
    float4 r;
    r.x = b0 * h0.x + b1 * h1.x + b2 * h2.x + b3 * h3.x;
    r.y = b0 * h0.y + b1 * h1.y + b2 * h2.y + b3 * h3.y;
    r.z = b0 * h0.z + b1 * h1.z + b2 * h2.z + b3 * h3.z;
    r.w = b0 * h0.w + b1 * h1.w + b2 * h2.w + b3 * h3.w;
    ((float4*)out)[i] = r;
    if (outh) {
        __nv_bfloat162 lo = __floats2bfloat162_rn(r.x, r.y);
        __nv_bfloat162 hi = __floats2bfloat162_rn(r.z, r.w);
        uint2 u;
        u.x = *reinterpret_cast<unsigned*>(&lo);
        u.y = *reinterpret_cast<unsigned*>(&hi);
        ((uint2*)outh)[i] = u;
    }
}

// fp32 -> bf16 shadow copy
__global__ void tobf16_k(const float* __restrict__ in, __nv_bfloat16* __restrict__ out)
{
    const int i = blockIdx.x * 256 + threadIdx.x;
    float4 v = ((const float4*)in)[i];
    __nv_bfloat162 lo = __floats2bfloat162_rn(v.x, v.y);
    __nv_bfloat162 hi = __floats2bfloat162_rn(v.z, v.w);
    uint2 u;
    u.x = *reinterpret_cast<unsigned*>(&lo);
    u.y = *reinterpret_cast<unsigned*>(&hi);
    ((uint2*)out)[i] = u;
}

extern "C" void kernel_launch(void* const* d_in, const int* in_sizes, int n_in,
                              void* d_out, int out_size)
{
    (void)in_sizes; (void)n_in; (void)out_size;

    const float* user    = (const float*)d_in[0];
    const float* product = (const float*)d_in[1];
    const float* V   = (const float*)d_in[2];
    const float* X   = (const float*)d_in[3];
    const float* Wp  = (const float*)d_in[4];
    const float* Bp  = (const float*)d_in[5];
    const float* Wq  = (const float*)d_in[6];
    const float* Bq  = (const float*)d_in[7];
    const float* Q   = (const float*)d_in[8];
    const int* unbrs = (const int*)d_in[9];
    const int* pnbrs = (const int*)d_in[10];
    float* out = (float*)d_out;

    float *dPS, *dH, *dPart;
    __nv_bfloat16 *dPNh, *dOtherh;
    cudaGetSymbolAddress((void**)&dPS,     g_PS);
    cudaGetSymbolAddress((void**)&dPNh,    g_PNh);
    cudaGetSymbolAddress((void**)&dOtherh, g_otherh);
    cudaGetSymbolAddress((void**)&dH,      g_H);
    cudaGetSymbolAddress((void**)&dPart,   g_part);

    cudaFuncSetAttribute(gemm_tc<0>, cudaFuncAttributeMaxDynamicSharedMemorySize, SMEM_BYTES);
    cudaFuncSetAttribute(gemm_tc<1>, cudaFuncAttributeMaxDynamicSharedMemorySize, SMEM_BYTES);

    // bf16 shadow of product for phase-0 gathers
    tobf16_k<<<NOTHER * EDIM / 4 / 256, 256>>>(product, dOtherh);

    for (int p = 0; p < 2; p++) {
        const float* src   = (p == 0) ? user    : product;
        const float* other = (p == 0) ? product : out;       // phase 2 attends over user_out
        const int*   nbrs  = (p == 0) ? unbrs   : pnbrs;
        const float* Vp  = V  + (size_t)p * MPATH * EDIM * DDIM;
        const float* Xp  = X  + (size_t)p * MPATH * DDIM;
        const float* Wpp = Wp + (size_t)p * MPATH * EDIM * DDIM;
        const float* Bpp = Bp + (size_t)p * MPATH * DDIM;
        const float* Wqp = Wq + (size_t)p * MPATH * EDIM * DDIM;
        const float* Bqp = Bq + (size_t)p * MPATH * DDIM;
        const float* Qp  = Q  + (size_t)p * MPATH * DDIM;
        float* outp = out + (size_t)p * NROW * EDIM;

        // PS = src@V (fp32, z=0) and PNh = bf16(other@W_p) (z=1) in ONE launch
        gemm_tc<0><<<dim3(NROW / 128, MPATH, 2), 256, SMEM_BYTES>>>(
            src, Vp, dPS, other, Wpp, dPNh, nullptr, nullptr, 0);
        attn_k<<<MPATH * NROW / 8, 256>>>(dPS, dPNh, Bpp, Xp, src, dOtherh, nbrs, dH);
        gemm_tc<1><<<dim3(NROW / 128, MPATH, 1), 256, SMEM_BYTES>>>(
            dH, Wqp, dPart, nullptr, nullptr, nullptr, Bqp, Qp, 1);
        combine_k<<<NROW * EDIM / 4 / 256, 256>>>(
            dH, dPart, NROW / 128, outp, (p == 0) ? dOtherh : nullptr);
    }
}

// round 5
// speedup vs baseline: 1.3288x; 1.0004x over previous
#include <cuda_runtime.h>
#include <cuda_bf16.h>
#include <mma.h>
#include <cstddef>

using namespace nvcuda;

#define NROW   8192
#define NOTHER 8192
#define EDIM   128
#define DDIM   64
#define KNBR   32
#define MPATH  4

#define LDA 136            // padded A smem stride (floats)
#define LDW 72             // padded W/C smem stride (floats)
#define SMEM_BYTES ((128 * LDA + 128 * LDW) * 4)

// Scratch (device globals: allocation-free rule)
__device__ float g_PS[(size_t)MPATH * NROW * DDIM];              // src @ V        (fp32)
__device__ __nv_bfloat16 g_PNh[(size_t)MPATH * NOTHER * DDIM];   // other @ W_p    (bf16)
__device__ __nv_bfloat16 g_otherh[(size_t)NOTHER * EDIM];        // bf16 shadow of gather target
__device__ float g_H [(size_t)MPATH * NROW * EDIM];              // H              (fp32)
__device__ float g_part[MPATH * 64];                             // sem partial sums

__device__ __forceinline__ float tanha(float x) {
    float y;
    asm("tanh.approx.f32 %0, %1;" : "=f"(y) : "f"(x));
    return y;
}

// ---------------------------------------------------------------------------
// Tensor-core GEMM (tf32 wmma, m16n16k8). Per (m, row-tile): C = A @ W[m].
//   Block: 256 threads (8 warps). Tile: 128 rows x 64 cols, full K=128 in smem.
//   MODE 0, z=0: outF[m][n][d] = C            (fp32, PS path)
//   MODE 0, z=1: outH[m][n][d] = bf16(C)      (bf16, PN path; A1/W1 operands)
//   MODE 1:      outF[m*gridDim.x+bx] = sum_rows sum_d tanh(C+bias[m][d])*Qv[m][d]
// ---------------------------------------------------------------------------
template <int MODE>
__global__ void __launch_bounds__(256) gemm_tc(
    const float* __restrict__ A0, const float* __restrict__ W0, float* __restrict__ outF,
    const float* __restrict__ A1, const float* __restrict__ W1, __nv_bfloat16* __restrict__ outH,
    const float* __restrict__ bias, const float* __restrict__ Qv, int aPerM)
{
    extern __shared__ float sm[];
    float* As = sm;                 // [128][LDA]
    float* Ws = sm + 128 * LDA;     // [128][LDW], reused as C staging

    const int m  = blockIdx.y;
    const int n0 = blockIdx.x * 128;
    const int tid = threadIdx.x;
    const int wid = tid >> 5;
    const int z = (MODE == 0) ? blockIdx.z : 0;

    const float* A = (z == 1) ? A1 : A0;
    const float* W = ((z == 1) ? W1 : W0) + (size_t)m * EDIM * DDIM;
    if (aPerM) A += (size_t)m * NROW * EDIM;

    __shared__ float sB[DDIM], sQ[DDIM], red[8];
    if (MODE == 1 && tid < DDIM) {
        sB[tid] = bias[m * DDIM + tid];
        sQ[tid] = Qv[m * DDIM + tid];
    }

    // Load A tile (128x128) -> smem (tf32-rounded)
#pragma unroll
    for (int i = 0; i < 16; i++) {
        int li = tid + i * 256;            // float4 index, 4096 total
        int r = li >> 5, c4 = (li & 31) << 2;
        float4 v = *(const float4*)(A + (size_t)(n0 + r) * EDIM + c4);
        float* d = As + r * LDA + c4;
        d[0] = wmma::__float_to_tf32(v.x);
        d[1] = wmma::__float_to_tf32(v.y);
        d[2] = wmma::__float_to_tf32(v.z);
        d[3] = wmma::__float_to_tf32(v.w);
    }
    // Load W (128x64) -> smem
#pragma unroll
    for (int i = 0; i < 8; i++) {
        int li = tid + i * 256;            // float4 index, 2048 total
        int r = li >> 4, c4 = (li & 15) << 2;
        float4 v = *(const float4*)(W + (size_t)r * DDIM + c4);
        float* d = Ws + r * LDW + c4;
        d[0] = wmma::__float_to_tf32(v.x);
        d[1] = wmma::__float_to_tf32(v.y);
        d[2] = wmma::__float_to_tf32(v.z);
        d[3] = wmma::__float_to_tf32(v.w);
    }
    __syncthreads();

    wmma::fragment<wmma::accumulator, 16, 16, 8, float> acc[4];
#pragma unroll
    for (int t = 0; t < 4; t++) wmma::fill_fragment(acc[t], 0.f);

    const int row0 = wid * 16;
#pragma unroll
    for (int k = 0; k < 16; k++) {
        wmma::fragment<wmma::matrix_a, 16, 16, 8, wmma::precision::tf32, wmma::row_major> af;
        wmma::load_matrix_sync(af, As + row0 * LDA + k * 8, LDA);
#pragma unroll
        for (int t = 0; t < 4; t++) {
            wmma::fragment<wmma::matrix_b, 16, 16, 8, wmma::precision::tf32, wmma::row_major> bf;
            wmma::load_matrix_sync(bf, Ws + (k * 8) * LDW + t * 16, LDW);
            wmma::mma_sync(acc[t], af, bf, acc[t]);
        }
    }

    if (MODE == 0 && z == 0) {
#pragma unroll
        for (int t = 0; t < 4; t++) {
            wmma::store_matrix_sync(
                outF + ((size_t)m * NROW + n0 + row0) * DDIM + t * 16,
                acc[t], DDIM, wmma::mem_row_major);
        }
    } else if (MODE == 0) {
        // bf16 output: stage C in smem (Ws free now), convert
        __syncthreads();
#pragma unroll
        for (int t = 0; t < 4; t++)
            wmma::store_matrix_sync(Ws + row0 * LDW + t * 16, acc[t], LDW, wmma::mem_row_major);
        __syncthreads();
#pragma unroll
        for (int i = 0; i < 16; i++) {
            int li = tid + i * 256;          // pair index over 4096 pairs
            int r = li >> 5, c2 = (li & 31) << 1;
            __nv_bfloat162 b = __floats2bfloat162_rn(Ws[r * LDW + c2], Ws[r * LDW + c2 + 1]);
            *(__nv_bfloat162*)(outH + ((size_t)m * NROW + n0 + r) * DDIM + c2) = b;
        }
    } else {
        __syncthreads();
#pragma unroll
        for (int t = 0; t < 4; t++)
            wmma::store_matrix_sync(Ws + row0 * LDW + t * 16, acc[t], LDW, wmma::mem_row_major);
        __syncthreads();

        float sv = 0.f;
#pragma unroll 4
        for (int li = tid; li < 128 * 64; li += 256) {
            int r = li >> 6, d = li & 63;
            sv += tanha(Ws[r * LDW + d] + sB[d]) * sQ[d];
        }
        sv += __shfl_xor_sync(0xffffffffu, sv, 16);
        sv += __shfl_xor_sync(0xffffffffu, sv, 8);
        sv += __shfl_xor_sync(0xffffffffu, sv, 4);
        sv += __shfl_xor_sync(0xffffffffu, sv, 2);
        sv += __shfl_xor_sync(0xffffffffu, sv, 1);
        if ((tid & 31) == 0) red[wid] = sv;
        __syncthreads();
        if (tid == 0) {
            float s = 0.f;
#pragma unroll
            for (int i = 0; i < 8; i++) s += red[i];
            outF[m * gridDim.x + blockIdx.x] = s;
        }
    }
}

// ---------------------------------------------------------------------------
// Attention + aggregation: one warp per (m, n). bf16 gathers.
//   Lane owns dims (2l, 2l+1) for scores, dims (4l..4l+3) for aggregation.
// ---------------------------------------------------------------------------
__global__ void __launch_bounds__(256) attn_k(
    const float* __restrict__ PS,
    const __nv_bfloat16* __restrict__ PNh,
    const float* __restrict__ Bp,     // [M][64]
    const float* __restrict__ X,      // [M][64]
    const float* __restrict__ src,    // [NROW][128]
    const __nv_bfloat16* __restrict__ otherh,  // [NOTHER][128] bf16
    const int*   __restrict__ nbrs,   // [M][NROW][K]
    float* __restrict__ H)
{
    const int w    = blockIdx.x * 8 + (threadIdx.x >> 5);
    const int lane = threadIdx.x & 31;
    const int m = w >> 13;
    const int n = w & (NROW - 1);
    const size_t base = (size_t)m * NROW + n;

    float2 psv = *(const float2*)(PS + base * DDIM + 2 * lane);
    float2 bpv = *(const float2*)(Bp + m * DDIM + 2 * lane);
    const float ps0 = psv.x + bpv.x;
    const float ps1 = psv.y + bpv.y;
    const float2 xv = *(const float2*)(X + m * DDIM + 2 * lane);
    const int myidx  = nbrs[base * KNBR + lane];
    const __nv_bfloat16* PNm = PNh + (size_t)m * NOTHER * DDIM;

    float myscore = 0.f;
#pragma unroll
    for (int k = 0; k < KNBR; k++) {
        int idx = __shfl_sync(0xffffffffu, myidx, k);
        __nv_bfloat162 pn = *(const __nv_bfloat162*)(PNm + (size_t)idx * DDIM + 2 * lane);
        float t0 = tanha(ps0 + __low2float(pn));
        float t1 = tanha(ps1 + __high2float(pn));
        float p = t0 * xv.x + t1 * xv.y;
        p += __shfl_xor_sync(0xffffffffu, p, 16);
        p += __shfl_xor_sync(0xffffffffu, p, 8);
        p += __shfl_xor_sync(0xffffffffu, p, 4);
        p += __shfl_xor_sync(0xffffffffu, p, 2);
        p += __shfl_xor_sync(0xffffffffu, p, 1);
        if (lane == k) myscore = p;
    }

    const float baseline = (m == 0) ? -1e-9f : 1.220703125e-4f;  // 1/8192
    float mx = myscore;
    mx = fmaxf(mx, __shfl_xor_sync(0xffffffffu, mx, 16));
    mx = fmaxf(mx, __shfl_xor_sync(0xffffffffu, mx, 8));
    mx = fmaxf(mx, __shfl_xor_sync(0xffffffffu, mx, 4));
    mx = fmaxf(mx, __shfl_xor_sync(0xffffffffu, mx, 2));
    mx = fmaxf(mx, __shfl_xor_sync(0xffffffffu, mx, 1));
    mx = fmaxf(mx, baseline);

    float e = __expf(myscore - mx);
    float s = e;
    s += __shfl_xor_sync(0xffffffffu, s, 16);
    s += __shfl_xor_sync(0xffffffffu, s, 8);
    s += __shfl_xor_sync(0xffffffffu, s, 4);
    s += __shfl_xor_sync(0xffffffffu, s, 2);
    s += __shfl_xor_sync(0xffffffffu, s, 1);
    const float denom = s + (float)(NOTHER - KNBR) * __expf(baseline - mx);
    const float a = e / denom;   // lane k holds A_k

    const float4* src4 = (const float4*)src;
    float4 acc = src4[(size_t)n * 32 + lane];
#pragma unroll
    for (int k = 0; k < KNBR; k++) {
        float ak = __shfl_sync(0xffffffffu, a, k);
        int idx  = __shfl_sync(0xffffffffu, myidx, k);
        uint2 u = *(const uint2*)(otherh + (size_t)idx * EDIM + lane * 4);
        __nv_bfloat162 v01 = *reinterpret_cast<__nv_bfloat162*>(&u.x);
        __nv_bfloat162 v23 = *reinterpret_cast<__nv_bfloat162*>(&u.y);
        acc.x += ak * __low2float(v01);
        acc.y += ak * __high2float(v01);
        acc.z += ak * __low2float(v23);
        acc.w += ak * __high2float(v23);
    }
    ((float4*)H)[base * 32 + lane] = acc;
}

// ---------------------------------------------------------------------------
// combine: beta = softmax_m(mean partials), out[n,e] = sum_m beta[m]*H[m,n,e].
// Optionally writes a bf16 shadow of out (for next phase's gathers).
// ---------------------------------------------------------------------------
__global__ void __launch_bounds__(256) combine_k(
    const float* __restrict__ H, const float* __restrict__ part, int nblk,
    float* __restrict__ out, __nv_bfloat16* __restrict__ outh)
{
    __shared__ float sp[256];
    __shared__ float sb[MPATH];
    const int tid = threadIdx.x;
    if (tid < MPATH * 64) sp[tid] = part[tid];
    __syncthreads();
    if (tid == 0) {
        float raw[MPATH];
#pragma unroll
        for (int mm = 0; mm < MPATH; mm++) {
            float s = 0.f;
            for (int j = 0; j < nblk; j++) s += sp[mm * nblk + j];
            raw[mm] = s * (1.f / (float)NROW);
        }
        float mx = fmaxf(fmaxf(raw[0], raw[1]), fmaxf(raw[2], raw[3]));
        float e0 = expf(raw[0] - mx), e1 = expf(raw[1] - mx);
        float e2 = expf(raw[2] - mx), e3 = expf(raw[3] - mx);
        float dn = e0 + e1 + e2 + e3;
        sb[0] = e0 / dn; sb[1] = e1 / dn; sb[2] = e2 / dn; sb[3] = e3 / dn;
    }
    __syncthreads();

    const int i = blockIdx.x * 256 + tid;
    const int S = NROW * EDIM / 4;
    const float b0 = sb[0], b1 = sb[1], b2 = sb[2], b3 = sb[3];
    const float4* H4 = (const float4*)H;
    float4 h0 = H4[i], h1 = H4[i + S], h2 = H4[i + 2 * S], h3 = H4[i + 3 * S];
    float4 r;
    r.x = b0 * h0.x + b1 * h1.x + b2 * h2.x + b3 * h3.x;
    r.y = b0 * h0.y + b1 * h1.y + b2 * h2.y + b3 * h3.y;
    r.z = b0 * h0.z + b1 * h1.z + b2 * h2.z + b3 * h3.z;
    r.w = b0 * h0.w + b1 * h1.w + b2 * h2.w + b3 * h3.w;
    ((float4*)out)[i] = r;
    if (outh) {
        __nv_bfloat162 lo = __floats2bfloat162_rn(r.x, r.y);
        __nv_bfloat162 hi = __floats2bfloat162_rn(r.z, r.w);
        uint2 u;
        u.x = *reinterpret_cast<unsigned*>(&lo);
        u.y = *reinterpret_cast<unsigned*>(&hi);
        ((uint2*)outh)[i] = u;
    }
}

// fp32 -> bf16 shadow copy
__global__ void tobf16_k(const float* __restrict__ in, __nv_bfloat16* __restrict__ out)
{
    const int i = blockIdx.x * 256 + threadIdx.x;
    float4 v = ((const float4*)in)[i];
    __nv_bfloat162 lo = __floats2bfloat162_rn(v.x, v.y);
    __nv_bfloat162 hi = __floats2bfloat162_rn(v.z, v.w);
    uint2 u;
    u.x = *reinterpret_cast<unsigned*>(&lo);
    u.y = *reinterpret_cast<unsigned*>(&hi);
    ((uint2*)out)[i] = u;
}

extern "C" void kernel_launch(void* const* d_in, const int* in_sizes, int n_in,
                              void* d_out, int out_size)
{
    (void)in_sizes; (void)n_in; (void)out_size;

    const float* user    = (const float*)d_in[0];
    const float* product = (const float*)d_in[1];
    const float* V   = (const float*)d_in[2];
    const float* X   = (const float*)d_in[3];
    const float* Wp  = (const float*)d_in[4];
    const float* Bp  = (const float*)d_in[5];
    const float* Wq  = (const float*)d_in[6];
    const float* Bq  = (const float*)d_in[7];
    const float* Q   = (const float*)d_in[8];
    const int* unbrs = (const int*)d_in[9];
    const int* pnbrs = (const int*)d_in[10];
    float* out = (float*)d_out;

    float *dPS, *dH, *dPart;
    __nv_bfloat16 *dPNh, *dOtherh;
    cudaGetSymbolAddress((void**)&dPS,     g_PS);
    cudaGetSymbolAddress((void**)&dPNh,    g_PNh);
    cudaGetSymbolAddress((void**)&dOtherh, g_otherh);
    cudaGetSymbolAddress((void**)&dH,      g_H);
    cudaGetSymbolAddress((void**)&dPart,   g_part);

    cudaFuncSetAttribute(gemm_tc<0>, cudaFuncAttributeMaxDynamicSharedMemorySize, SMEM_BYTES);
    cudaFuncSetAttribute(gemm_tc<1>, cudaFuncAttributeMaxDynamicSharedMemorySize, SMEM_BYTES);

    // bf16 shadow of product for phase-0 gathers
    tobf16_k<<<NOTHER * EDIM / 4 / 256, 256>>>(product, dOtherh);

    for (int p = 0; p < 2; p++) {
        const float* src   = (p == 0) ? user    : product;
        const float* other = (p == 0) ? product : out;       // phase 2 attends over user_out
        const int*   nbrs  = (p == 0) ? unbrs   : pnbrs;
        const float* Vp  = V  + (size_t)p * MPATH * EDIM * DDIM;
        const float* Xp  = X  + (size_t)p * MPATH * DDIM;
        const float* Wpp = Wp + (size_t)p * MPATH * EDIM * DDIM;
        const float* Bpp = Bp + (size_t)p * MPATH * DDIM;
        const float* Wqp = Wq + (size_t)p * MPATH * EDIM * DDIM;
        const float* Bqp = Bq + (size_t)p * MPATH * DDIM;
        const float* Qp  = Q  + (size_t)p * MPATH * DDIM;
        float* outp = out + (size_t)p * NROW * EDIM;

        // PS = src@V (fp32, z=0) and PNh = bf16(other@W_p) (z=1) in ONE launch
        gemm_tc<0><<<dim3(NROW / 128, MPATH, 2), 256, SMEM_BYTES>>>(
            src, Vp, dPS, other, Wpp, dPNh, nullptr, nullptr, 0);
        attn_k<<<MPATH * NROW / 8, 256>>>(dPS, dPNh, Bpp, Xp, src, dOtherh, nbrs, dH);
        gemm_tc<1><<<dim3(NROW / 128, MPATH, 1), 256, SMEM_BYTES>>>(
            dH, Wqp, dPart, nullptr, nullptr, nullptr, Bqp, Qp, 1);
        combine_k<<<NROW * EDIM / 4 / 256, 256>>>(
            dH, dPart, NROW / 128, outp, (p == 0) ? dOtherh : nullptr);
    }
}

// round 6
// speedup vs baseline: 1.3386x; 1.0074x over previous
#include <cuda_runtime.h>
#include <cuda_bf16.h>
#include <mma.h>
#include <cstddef>

using namespace nvcuda;

#define NROW   8192
#define NOTHER 8192
#define EDIM   128
#define DDIM   64
#define KNBR   32
#define MPATH  4

#define LDA 136            // padded A smem stride (floats)
#define LDW 72             // padded W/C smem stride (floats)
#define SMEM_BYTES ((128 * LDA + 128 * LDW) * 4)

// Scratch (device globals: allocation-free rule)
__device__ float g_PS[(size_t)MPATH * NROW * DDIM];              // src @ V        (fp32)
__device__ __nv_bfloat16 g_PNh[(size_t)MPATH * NOTHER * DDIM];   // other @ W_p    (bf16)
__device__ __nv_bfloat16 g_otherh[(size_t)NOTHER * EDIM];        // bf16 shadow of gather target
__device__ float g_H [(size_t)MPATH * NROW * EDIM];              // H              (fp32)
__device__ float g_part[MPATH * 64];                             // sem partial sums

__device__ __forceinline__ float tanha(float x) {
    float y;
    asm("tanh.approx.f32 %0, %1;" : "=f"(y) : "f"(x));
    return y;
}

// ---------------------------------------------------------------------------
// Tensor-core GEMM (tf32 wmma, m16n16k8). Per (m, row-tile): C = A @ W[m].
//   Block: 256 threads (8 warps). Tile: 128 rows x 64 cols, full K=128 in smem.
//   MODE 0, z=0: outF[m][n][d] = C            (fp32, PS path)
//   MODE 0, z=1: outH[m][n][d] = bf16(C)      (bf16, PN path; A1/W1 operands)
//   MODE 1:      outF[m*gridDim.x+bx] = sum_rows sum_d tanh(C+bias[m][d])*Qv[m][d]
// ---------------------------------------------------------------------------
template <int MODE>
__global__ void __launch_bounds__(256) gemm_tc(
    const float* __restrict__ A0, const float* __restrict__ W0, float* __restrict__ outF,
    const float* __restrict__ A1, const float* __restrict__ W1, __nv_bfloat16* __restrict__ outH,
    const float* __restrict__ bias, const float* __restrict__ Qv, int aPerM)
{
    extern __shared__ float sm[];
    float* As = sm;                 // [128][LDA]
    float* Ws = sm + 128 * LDA;     // [128][LDW], reused as C staging

    const int m  = blockIdx.y;
    const int n0 = blockIdx.x * 128;
    const int tid = threadIdx.x;
    const int wid = tid >> 5;
    const int z = (MODE == 0) ? blockIdx.z : 0;

    const float* A = (z == 1) ? A1 : A0;
    const float* W = ((z == 1) ? W1 : W0) + (size_t)m * EDIM * DDIM;
    if (aPerM) A += (size_t)m * NROW * EDIM;

    __shared__ float sB[DDIM], sQ[DDIM], red[8];
    if (MODE == 1 && tid < DDIM) {
        sB[tid] = bias[m * DDIM + tid];
        sQ[tid] = Qv[m * DDIM + tid];
    }

    // Load A tile (128x128) -> smem (tf32-rounded)
#pragma unroll
    for (int i = 0; i < 16; i++) {
        int li = tid + i * 256;            // float4 index, 4096 total
        int r = li >> 5, c4 = (li & 31) << 2;
        float4 v = *(const float4*)(A + (size_t)(n0 + r) * EDIM + c4);
        float* d = As + r * LDA + c4;
        d[0] = wmma::__float_to_tf32(v.x);
        d[1] = wmma::__float_to_tf32(v.y);
        d[2] = wmma::__float_to_tf32(v.z);
        d[3] = wmma::__float_to_tf32(v.w);
    }
    // Load W (128x64) -> smem
#pragma unroll
    for (int i = 0; i < 8; i++) {
        int li = tid + i * 256;            // float4 index, 2048 total
        int r = li >> 4, c4 = (li & 15) << 2;
        float4 v = *(const float4*)(W + (size_t)r * DDIM + c4);
        float* d = Ws + r * LDW + c4;
        d[0] = wmma::__float_to_tf32(v.x);
        d[1] = wmma::__float_to_tf32(v.y);
        d[2] = wmma::__float_to_tf32(v.z);
        d[3] = wmma::__float_to_tf32(v.w);
    }
    __syncthreads();

    wmma::fragment<wmma::accumulator, 16, 16, 8, float> acc[4];
#pragma unroll
    for (int t = 0; t < 4; t++) wmma::fill_fragment(acc[t], 0.f);

    const int row0 = wid * 16;
#pragma unroll
    for (int k = 0; k < 16; k++) {
        wmma::fragment<wmma::matrix_a, 16, 16, 8, wmma::precision::tf32, wmma::row_major> af;
        wmma::load_matrix_sync(af, As + row0 * LDA + k * 8, LDA);
#pragma unroll
        for (int t = 0; t < 4; t++) {
            wmma::fragment<wmma::matrix_b, 16, 16, 8, wmma::precision::tf32, wmma::row_major> bf;
            wmma::load_matrix_sync(bf, Ws + (k * 8) * LDW + t * 16, LDW);
            wmma::mma_sync(acc[t], af, bf, acc[t]);
        }
    }

    if (MODE == 0 && z == 0) {
#pragma unroll
        for (int t = 0; t < 4; t++) {
            wmma::store_matrix_sync(
                outF + ((size_t)m * NROW + n0 + row0) * DDIM + t * 16,
                acc[t], DDIM, wmma::mem_row_major);
        }
    } else if (MODE == 0) {
        // bf16 output: stage C in smem (Ws free now), convert
        __syncthreads();
#pragma unroll
        for (int t = 0; t < 4; t++)
            wmma::store_matrix_sync(Ws + row0 * LDW + t * 16, acc[t], LDW, wmma::mem_row_major);
        __syncthreads();
#pragma unroll
        for (int i = 0; i < 16; i++) {
            int li = tid + i * 256;          // pair index over 4096 pairs
            int r = li >> 5, c2 = (li & 31) << 1;
            __nv_bfloat162 b = __floats2bfloat162_rn(Ws[r * LDW + c2], Ws[r * LDW + c2 + 1]);
            *(__nv_bfloat162*)(outH + ((size_t)m * NROW + n0 + r) * DDIM + c2) = b;
        }
    } else {
        __syncthreads();
#pragma unroll
        for (int t = 0; t < 4; t++)
            wmma::store_matrix_sync(Ws + row0 * LDW + t * 16, acc[t], LDW, wmma::mem_row_major);
        __syncthreads();

        float sv = 0.f;
#pragma unroll 4
        for (int li = tid; li < 128 * 64; li += 256) {
            int r = li >> 6, d = li & 63;
            sv += tanha(Ws[r * LDW + d] + sB[d]) * sQ[d];
        }
        sv += __shfl_xor_sync(0xffffffffu, sv, 16);
        sv += __shfl_xor_sync(0xffffffffu, sv, 8);
        sv += __shfl_xor_sync(0xffffffffu, sv, 4);
        sv += __shfl_xor_sync(0xffffffffu, sv, 2);
        sv += __shfl_xor_sync(0xffffffffu, sv, 1);
        if ((tid & 31) == 0) red[wid] = sv;
        __syncthreads();
        if (tid == 0) {
            float s = 0.f;
#pragma unroll
            for (int i = 0; i < 8; i++) s += red[i];
            outF[m * gridDim.x + blockIdx.x] = s;
        }
    }
}

// ---------------------------------------------------------------------------
// Attention + aggregation: one warp per (m, n). bf16 gathers.
//   Lane owns dims (2l, 2l+1) for scores, dims (4l..4l+3) for aggregation.
// ---------------------------------------------------------------------------
__global__ void __launch_bounds__(256) attn_k(
    const float* __restrict__ PS,
    const __nv_bfloat16* __restrict__ PNh,
    const float* __restrict__ Bp,     // [M][64]
    const float* __restrict__ X,      // [M][64]
    const float* __restrict__ src,    // [NROW][128]
    const __nv_bfloat16* __restrict__ otherh,  // [NOTHER][128] bf16
    const int*   __restrict__ nbrs,   // [M][NROW][K]
    float* __restrict__ H)
{
    const int w    = blockIdx.x * 8 + (threadIdx.x >> 5);
    const int lane = threadIdx.x & 31;
    const int m = w >> 13;
    const int n = w & (NROW - 1);
    const size_t base = (size_t)m * NROW + n;

    float2 psv = *(const float2*)(PS + base * DDIM + 2 * lane);
    float2 bpv = *(const float2*)(Bp + m * DDIM + 2 * lane);
    const float ps0 = psv.x + bpv.x;
    const float ps1 = psv.y + bpv.y;
    const float2 xv = *(const float2*)(X + m * DDIM + 2 * lane);
    const int myidx  = nbrs[base * KNBR + lane];
    const __nv_bfloat16* PNm = PNh + (size_t)m * NOTHER * DDIM;

    float myscore = 0.f;
#pragma unroll
    for (int k = 0; k < KNBR; k++) {
        int idx = __shfl_sync(0xffffffffu, myidx, k);
        __nv_bfloat162 pn = *(const __nv_bfloat162*)(PNm + (size_t)idx * DDIM + 2 * lane);
        float t0 = tanha(ps0 + __low2float(pn));
        float t1 = tanha(ps1 + __high2float(pn));
        float p = t0 * xv.x + t1 * xv.y;
        p += __shfl_xor_sync(0xffffffffu, p, 16);
        p += __shfl_xor_sync(0xffffffffu, p, 8);
        p += __shfl_xor_sync(0xffffffffu, p, 4);
        p += __shfl_xor_sync(0xffffffffu, p, 2);
        p += __shfl_xor_sync(0xffffffffu, p, 1);
        if (lane == k) myscore = p;
    }

    const float baseline = (m == 0) ? -1e-9f : 1.220703125e-4f;  // 1/8192
    float mx = myscore;
    mx = fmaxf(mx, __shfl_xor_sync(0xffffffffu, mx, 16));
    mx = fmaxf(mx, __shfl_xor_sync(0xffffffffu, mx, 8));
    mx = fmaxf(mx, __shfl_xor_sync(0xffffffffu, mx, 4));
    mx = fmaxf(mx, __shfl_xor_sync(0xffffffffu, mx, 2));
    mx = fmaxf(mx, __shfl_xor_sync(0xffffffffu, mx, 1));
    mx = fmaxf(mx, baseline);

    float e = __expf(myscore - mx);
    float s = e;
    s += __shfl_xor_sync(0xffffffffu, s, 16);
    s += __shfl_xor_sync(0xffffffffu, s, 8);
    s += __shfl_xor_sync(0xffffffffu, s, 4);
    s += __shfl_xor_sync(0xffffffffu, s, 2);
    s += __shfl_xor_sync(0xffffffffu, s, 1);
    const float denom = s + (float)(NOTHER - KNBR) * __expf(baseline - mx);
    const float a = e / denom;   // lane k holds A_k

    const float4* src4 = (const float4*)src;
    float4 acc = src4[(size_t)n * 32 + lane];
#pragma unroll
    for (int k = 0; k < KNBR; k++) {
        float ak = __shfl_sync(0xffffffffu, a, k);
        int idx  = __shfl_sync(0xffffffffu, myidx, k);
        uint2 u = *(const uint2*)(otherh + (size_t)idx * EDIM + lane * 4);
        __nv_bfloat162 v01 = *reinterpret_cast<__nv_bfloat162*>(&u.x);
        __nv_bfloat162 v23 = *reinterpret_cast<__nv_bfloat162*>(&u.y);
        acc.x += ak * __low2float(v01);
        acc.y += ak * __high2float(v01);
        acc.z += ak * __low2float(v23);
        acc.w += ak * __high2float(v23);
    }
    ((float4*)H)[base * 32 + lane] = acc;
}

// ---------------------------------------------------------------------------
// combine: beta = softmax_m(mean partials), out[n,e] = sum_m beta[m]*H[m,n,e].
// Optionally writes a bf16 shadow of out (for next phase's gathers).
// ---------------------------------------------------------------------------
__global__ void __launch_bounds__(256) combine_k(
    const float* __restrict__ H, const float* __restrict__ part, int nblk,
    float* __restrict__ out, __nv_bfloat16* __restrict__ outh)
{
    __shared__ float sp[256];
    __shared__ float sb[MPATH];
    const int tid = threadIdx.x;
    if (tid < MPATH * 64) sp[tid] = part[tid];
    __syncthreads();
    if (tid == 0) {
        float raw[MPATH];
#pragma unroll
        for (int mm = 0; mm < MPATH; mm++) {
            float s = 0.f;
            for (int j = 0; j < nblk; j++) s += sp[mm * nblk + j];
            raw[mm] = s * (1.f / (float)NROW);
        }
        float mx = fmaxf(fmaxf(raw[0], raw[1]), fmaxf(raw[2], raw[3]));
        float e0 = expf(raw[0] - mx), e1 = expf(raw[1] - mx);
        float e2 = expf(raw[2] - mx), e3 = expf(raw[3] - mx);
        float dn = e0 + e1 + e2 + e3;
        sb[0] = e0 / dn; sb[1] = e1 / dn; sb[2] = e2 / dn; sb[3] = e3 / dn;
    }
    __syncthreads();

    const int i = blockIdx.x * 256 + tid;
    const int S = NROW * EDIM / 4;
    const float b0 = sb[0], b1 = sb[1], b2 = sb[2], b3 = sb[3];
    const float4* H4 = (const float4*)H;
    float4 h0 = H4[i], h1 = H4[i + S], h2 = H4[i + 2 * S], h3 = H4[i + 3 * S];
    float4 r;
    r.x = b0 * h0.x + b1 * h1.x + b2 * h2.x + b3 * h3.x;
    r.y = b0 * h0.y + b1 * h1.y + b2 * h2.y + b3 * h3.y;
    r.z = b0 * h0.z + b1 * h1.z + b2 * h2.z + b3 * h3.z;
    r.w = b0 * h0.w + b1 * h1.w + b2 * h2.w + b3 * h3.w;
    ((float4*)out)[i] = r;
    if (outh) {
        __nv_bfloat162 lo = __floats2bfloat162_rn(r.x, r.y);
        __nv_bfloat162 hi = __floats2bfloat162_rn(r.z, r.w);
        uint2 u;
        u.x = *reinterpret_cast<unsigned*>(&lo);
        u.y = *reinterpret_cast<unsigned*>(&hi);
        ((uint2*)outh)[i] = u;
    }
}

// fp32 -> bf16 shadow copy
__global__ void tobf16_k(const float* __restrict__ in, __nv_bfloat16* __restrict__ out)
{
    const int i = blockIdx.x * 256 + threadIdx.x;
    float4 v = ((const float4*)in)[i];
    __nv_bfloat162 lo = __floats2bfloat162_rn(v.x, v.y);
    __nv_bfloat162 hi = __floats2bfloat162_rn(v.z, v.w);
    uint2 u;
    u.x = *reinterpret_cast<unsigned*>(&lo);
    u.y = *reinterpret_cast<unsigned*>(&hi);
    ((uint2*)out)[i] = u;
}

extern "C" void kernel_launch(void* const* d_in, const int* in_sizes, int n_in,
                              void* d_out, int out_size)
{
    (void)in_sizes; (void)n_in; (void)out_size;

    const float* user    = (const float*)d_in[0];
    const float* product = (const float*)d_in[1];
    const float* V   = (const float*)d_in[2];
    const float* X   = (const float*)d_in[3];
    const float* Wp  = (const float*)d_in[4];
    const float* Bp  = (const float*)d_in[5];
    const float* Wq  = (const float*)d_in[6];
    const float* Bq  = (const float*)d_in[7];
    const float* Q   = (const float*)d_in[8];
    const int* unbrs = (const int*)d_in[9];
    const int* pnbrs = (const int*)d_in[10];
    float* out = (float*)d_out;

    float *dPS, *dH, *dPart;
    __nv_bfloat16 *dPNh, *dOtherh;
    cudaGetSymbolAddress((void**)&dPS,     g_PS);
    cudaGetSymbolAddress((void**)&dPNh,    g_PNh);
    cudaGetSymbolAddress((void**)&dOtherh, g_otherh);
    cudaGetSymbolAddress((void**)&dH,      g_H);
    cudaGetSymbolAddress((void**)&dPart,   g_part);

    cudaFuncSetAttribute(gemm_tc<0>, cudaFuncAttributeMaxDynamicSharedMemorySize, SMEM_BYTES);
    cudaFuncSetAttribute(gemm_tc<1>, cudaFuncAttributeMaxDynamicSharedMemorySize, SMEM_BYTES);

    // bf16 shadow of product for phase-0 gathers
    tobf16_k<<<NOTHER * EDIM / 4 / 256, 256>>>(product, dOtherh);

    for (int p = 0; p < 2; p++) {
        const float* src   = (p == 0) ? user    : product;
        const float* other = (p == 0) ? product : out;       // phase 2 attends over user_out
        const int*   nbrs  = (p == 0) ? unbrs   : pnbrs;
        const float* Vp  = V  + (size_t)p * MPATH * EDIM * DDIM;
        const float* Xp  = X  + (size_t)p * MPATH * DDIM;
        const float* Wpp = Wp + (size_t)p * MPATH * EDIM * DDIM;
        const float* Bpp = Bp + (size_t)p * MPATH * DDIM;
        const float* Wqp = Wq + (size_t)p * MPATH * EDIM * DDIM;
        const float* Bqp = Bq + (size_t)p * MPATH * DDIM;
        const float* Qp  = Q  + (size_t)p * MPATH * DDIM;
        float* outp = out + (size_t)p * NROW * EDIM;

        // PS = src@V (fp32, z=0) and PNh = bf16(other@W_p) (z=1) in ONE launch
        gemm_tc<0><<<dim3(NROW / 128, MPATH, 2), 256, SMEM_BYTES>>>(
            src, Vp, dPS, other, Wpp, dPNh, nullptr, nullptr, 0);
        attn_k<<<MPATH * NROW / 8, 256>>>(dPS, dPNh, Bpp, Xp, src, dOtherh, nbrs, dH);
        gemm_tc<1><<<dim3(NROW / 128, MPATH, 1), 256, SMEM_BYTES>>>(
            dH, Wqp, dPart, nullptr, nullptr, nullptr, Bqp, Qp, 1);
        combine_k<<<NROW * EDIM / 4 / 256, 256>>>(
            dH, dPart, NROW / 128, outp, (p == 0) ? dOtherh : nullptr);
    }
}

// round 7
// speedup vs baseline: 1.4594x; 1.0902x over previous
#include <cuda_runtime.h>
#include <cuda_bf16.h>
#include <mma.h>
#include <cstddef>

using namespace nvcuda;

#define NROW   8192
#define NOTHER 8192
#define EDIM   128
#define DDIM   64
#define KNBR   32
#define MPATH  4

#define LDA_H 136          // A smem stride (bf16 elems)
#define LDW_H 72           // W smem stride (bf16 elems)
#define LDC_F 68           // C staging stride (floats), aliases As
#define SMEM_BYTES (128 * LDA_H * 2 + 128 * LDW_H * 2)   // 34816 + 18432 = 53248

// Scratch (device globals: allocation-free rule)
__device__ float g_PS[(size_t)MPATH * NROW * DDIM];              // src @ V        (fp32)
__device__ __nv_bfloat16 g_PNh[(size_t)MPATH * NOTHER * DDIM];   // other @ W_p    (bf16)
__device__ __nv_bfloat16 g_otherh[(size_t)NOTHER * EDIM];        // bf16 shadow of gather target
__device__ float g_H [(size_t)MPATH * NROW * EDIM];              // H              (fp32)
__device__ float g_part[MPATH * 64];                             // sem partial sums

__device__ __forceinline__ float tanha(float x) {
    float y;
    asm("tanh.approx.f32 %0, %1;" : "=f"(y) : "f"(x));
    return y;
}
__device__ __forceinline__ __nv_bfloat162 bfc(unsigned u) {
    return *reinterpret_cast<__nv_bfloat162*>(&u);
}

// ---------------------------------------------------------------------------
// Tensor-core GEMM (bf16 wmma, m16n16k16). Per (m, row-tile): C = A @ W[m].
//   Block: 256 threads (8 warps). Tile: 128 rows x 64 cols, full K=128 in smem.
//   MODE 0, z=0: outF[m][n][d] = C            (fp32, PS path)
//   MODE 0, z=1: outH[m][n][d] = bf16(C)      (bf16, PN path; A1/W1 operands)
//   MODE 1:      outF[m*gridDim.x+bx] = sum_rows sum_d tanh(C+bias[m][d])*Qv[m][d]
// ---------------------------------------------------------------------------
template <int MODE>
__global__ void __launch_bounds__(256) gemm_tc(
    const float* __restrict__ A0, const float* __restrict__ W0, float* __restrict__ outF,
    const float* __restrict__ A1, const float* __restrict__ W1, __nv_bfloat16* __restrict__ outH,
    const float* __restrict__ bias, const float* __restrict__ Qv, int aPerM)
{
    extern __shared__ char smraw[];
    __nv_bfloat16* As = (__nv_bfloat16*)smraw;                    // [128][LDA_H]
    __nv_bfloat16* Ws = (__nv_bfloat16*)(smraw + 128 * LDA_H * 2); // [128][LDW_H]
    float* Cs = (float*)smraw;                                     // aliases As, [128][LDC_F]

    const int m  = blockIdx.y;
    const int n0 = blockIdx.x * 128;
    const int tid = threadIdx.x;
    const int wid = tid >> 5;
    const int z = (MODE == 0) ? blockIdx.z : 0;

    const float* A = (z == 1) ? A1 : A0;
    const float* W = ((z == 1) ? W1 : W0) + (size_t)m * EDIM * DDIM;
    if (aPerM) A += (size_t)m * NROW * EDIM;

    __shared__ float sB[DDIM], sQ[DDIM], red[8];
    if (MODE == 1 && tid < DDIM) {
        sB[tid] = bias[m * DDIM + tid];
        sQ[tid] = Qv[m * DDIM + tid];
    }

    // Load A tile (128x128 fp32) -> bf16 smem
#pragma unroll
    for (int i = 0; i < 16; i++) {
        int li = tid + i * 256;            // float4 index, 4096 total
        int r = li >> 5, c4 = (li & 31) << 2;
        float4 v = *(const float4*)(A + (size_t)(n0 + r) * EDIM + c4);
        __nv_bfloat162 lo = __floats2bfloat162_rn(v.x, v.y);
        __nv_bfloat162 hi = __floats2bfloat162_rn(v.z, v.w);
        *(__nv_bfloat162*)(As + r * LDA_H + c4)     = lo;
        *(__nv_bfloat162*)(As + r * LDA_H + c4 + 2) = hi;
    }
    // Load W (128x64 fp32) -> bf16 smem
#pragma unroll
    for (int i = 0; i < 8; i++) {
        int li = tid + i * 256;            // float4 index, 2048 total
        int r = li >> 4, c4 = (li & 15) << 2;
        float4 v = *(const float4*)(W + (size_t)r * DDIM + c4);
        __nv_bfloat162 lo = __floats2bfloat162_rn(v.x, v.y);
        __nv_bfloat162 hi = __floats2bfloat162_rn(v.z, v.w);
        *(__nv_bfloat162*)(Ws + r * LDW_H + c4)     = lo;
        *(__nv_bfloat162*)(Ws + r * LDW_H + c4 + 2) = hi;
    }
    __syncthreads();

    wmma::fragment<wmma::accumulator, 16, 16, 16, float> acc[4];
#pragma unroll
    for (int t = 0; t < 4; t++) wmma::fill_fragment(acc[t], 0.f);

    const int row0 = wid * 16;
#pragma unroll
    for (int k = 0; k < 8; k++) {
        wmma::fragment<wmma::matrix_a, 16, 16, 16, __nv_bfloat16, wmma::row_major> af;
        wmma::load_matrix_sync(af, As + row0 * LDA_H + k * 16, LDA_H);
#pragma unroll
        for (int t = 0; t < 4; t++) {
            wmma::fragment<wmma::matrix_b, 16, 16, 16, __nv_bfloat16, wmma::row_major> bf;
            wmma::load_matrix_sync(bf, Ws + (k * 16) * LDW_H + t * 16, LDW_H);
            wmma::mma_sync(acc[t], af, bf, acc[t]);
        }
    }

    if (MODE == 0 && z == 0) {
#pragma unroll
        for (int t = 0; t < 4; t++) {
            wmma::store_matrix_sync(
                outF + ((size_t)m * NROW + n0 + row0) * DDIM + t * 16,
                acc[t], DDIM, wmma::mem_row_major);
        }
    } else if (MODE == 0) {
        // bf16 output: stage fp32 C in smem (aliases As; MMA reads done), convert
        __syncthreads();
#pragma unroll
        for (int t = 0; t < 4; t++)
            wmma::store_matrix_sync(Cs + row0 * LDC_F + t * 16, acc[t], LDC_F, wmma::mem_row_major);
        __syncthreads();
#pragma unroll
        for (int i = 0; i < 16; i++) {
            int li = tid + i * 256;          // pair index over 4096 pairs
            int r = li >> 5, c2 = (li & 31) << 1;
            __nv_bfloat162 b = __floats2bfloat162_rn(Cs[r * LDC_F + c2], Cs[r * LDC_F + c2 + 1]);
            *(__nv_bfloat162*)(outH + ((size_t)m * NROW + n0 + r) * DDIM + c2) = b;
        }
    } else {
        __syncthreads();
#pragma unroll
        for (int t = 0; t < 4; t++)
            wmma::store_matrix_sync(Cs + row0 * LDC_F + t * 16, acc[t], LDC_F, wmma::mem_row_major);
        __syncthreads();

        float sv = 0.f;
#pragma unroll 4
        for (int li = tid; li < 128 * 64; li += 256) {
            int r = li >> 6, d = li & 63;
            sv += tanha(Cs[r * LDC_F + d] + sB[d]) * sQ[d];
        }
        sv += __shfl_xor_sync(0xffffffffu, sv, 16);
        sv += __shfl_xor_sync(0xffffffffu, sv, 8);
        sv += __shfl_xor_sync(0xffffffffu, sv, 4);
        sv += __shfl_xor_sync(0xffffffffu, sv, 2);
        sv += __shfl_xor_sync(0xffffffffu, sv, 1);
        if ((tid & 31) == 0) red[wid] = sv;
        __syncthreads();
        if (tid == 0) {
            float s = 0.f;
#pragma unroll
            for (int i = 0; i < 8; i++) s += red[i];
            outF[m * gridDim.x + blockIdx.x] = s;
        }
    }
}

// ---------------------------------------------------------------------------
// Attention + aggregation: one warp per (m, n). LANE-PER-K scores (no shuffle
// chains in the inner loop): lane k accumulates its neighbor's score over d,
// reading psb/x broadcast from smem and the PN row contiguously.
// ---------------------------------------------------------------------------
__global__ void __launch_bounds__(256) attn_k(
    const float* __restrict__ PS,
    const __nv_bfloat16* __restrict__ PNh,
    const float* __restrict__ Bp,     // [M][64]
    const float* __restrict__ X,      // [M][64]
    const float* __restrict__ src,    // [NROW][128]
    const __nv_bfloat16* __restrict__ otherh,  // [NOTHER][128] bf16
    const int*   __restrict__ nbrs,   // [M][NROW][K]
    float* __restrict__ H)
{
    __shared__ float s_psb[8][64];
    __shared__ float s_x[64];

    const int wid  = threadIdx.x >> 5;
    const int lane = threadIdx.x & 31;
    const int w = blockIdx.x * 8 + wid;
    const int m = w >> 13;                 // all warps in block share m
    const int n = w & (NROW - 1);
    const size_t base = (size_t)m * NROW + n;

    // stage psb (PS + Bp) per warp, x per block
    {
        float2 psv = *(const float2*)(PS + base * DDIM + 2 * lane);
        float2 bpv = *(const float2*)(Bp + m * DDIM + 2 * lane);
        s_psb[wid][2 * lane]     = psv.x + bpv.x;
        s_psb[wid][2 * lane + 1] = psv.y + bpv.y;
        if (wid == 0) {
            float2 xv = *(const float2*)(X + m * DDIM + 2 * lane);
            s_x[2 * lane]     = xv.x;
            s_x[2 * lane + 1] = xv.y;
        }
    }
    __syncthreads();

    const int myidx = nbrs[base * KNBR + lane];
    const __nv_bfloat16* pnrow = PNh + ((size_t)m * NOTHER + myidx) * DDIM;
    const float4* ppsb = (const float4*)s_psb[wid];
    const float4* px   = (const float4*)s_x;

    float sc = 0.f;
#pragma unroll
    for (int j = 0; j < 8; j++) {
        uint4 u = *(const uint4*)(pnrow + j * 8);
        __nv_bfloat162 p0 = bfc(u.x), p1 = bfc(u.y), p2 = bfc(u.z), p3 = bfc(u.w);
        float4 b0 = ppsb[j * 2], b1 = ppsb[j * 2 + 1];
        float4 x0 = px[j * 2],   x1 = px[j * 2 + 1];
        sc += tanha(b0.x + __low2float(p0))  * x0.x;
        sc += tanha(b0.y + __high2float(p0)) * x0.y;
        sc += tanha(b0.z + __low2float(p1))  * x0.z;
        sc += tanha(b0.w + __high2float(p1)) * x0.w;
        sc += tanha(b1.x + __low2float(p2))  * x1.x;
        sc += tanha(b1.y + __high2float(p2)) * x1.y;
        sc += tanha(b1.z + __low2float(p3))  * x1.z;
        sc += tanha(b1.w + __high2float(p3)) * x1.w;
    }

    // softmax over the full axis (lane holds score for its own k)
    const float baseline = (m == 0) ? -1e-9f : 1.220703125e-4f;  // 1/8192
    float mx = sc;
    mx = fmaxf(mx, __shfl_xor_sync(0xffffffffu, mx, 16));
    mx = fmaxf(mx, __shfl_xor_sync(0xffffffffu, mx, 8));
    mx = fmaxf(mx, __shfl_xor_sync(0xffffffffu, mx, 4));
    mx = fmaxf(mx, __shfl_xor_sync(0xffffffffu, mx, 2));
    mx = fmaxf(mx, __shfl_xor_sync(0xffffffffu, mx, 1));
    mx = fmaxf(mx, baseline);

    float e = __expf(sc - mx);
    float s = e;
    s += __shfl_xor_sync(0xffffffffu, s, 16);
    s += __shfl_xor_sync(0xffffffffu, s, 8);
    s += __shfl_xor_sync(0xffffffffu, s, 4);
    s += __shfl_xor_sync(0xffffffffu, s, 2);
    s += __shfl_xor_sync(0xffffffffu, s, 1);
    const float denom = s + (float)(NOTHER - KNBR) * __expf(baseline - mx);
    const float a = e / denom;   // lane k holds A_k

    // aggregation: lanes split the 128 dims (4 each), broadcast a/idx per k
    const float4* src4 = (const float4*)src;
    float4 acc = src4[(size_t)n * 32 + lane];
#pragma unroll
    for (int k = 0; k < KNBR; k++) {
        float ak = __shfl_sync(0xffffffffu, a, k);
        int idx  = __shfl_sync(0xffffffffu, myidx, k);
        uint2 u = *(const uint2*)(otherh + (size_t)idx * EDIM + lane * 4);
        __nv_bfloat162 v01 = bfc(u.x);
        __nv_bfloat162 v23 = bfc(u.y);
        acc.x += ak * __low2float(v01);
        acc.y += ak * __high2float(v01);
        acc.z += ak * __low2float(v23);
        acc.w += ak * __high2float(v23);
    }
    ((float4*)H)[base * 32 + lane] = acc;
}

// ---------------------------------------------------------------------------
// combine: beta = softmax_m(mean partials), out[n,e] = sum_m beta[m]*H[m,n,e].
// Optionally writes a bf16 shadow of out (for next phase's gathers).
// ---------------------------------------------------------------------------
__global__ void __launch_bounds__(256) combine_k(
    const float* __restrict__ H, const float* __restrict__ part, int nblk,
    float* __restrict__ out, __nv_bfloat16* __restrict__ outh)
{
    __shared__ float sp[256];
    __shared__ float sb[MPATH];
    const int tid = threadIdx.x;
    if (tid < MPATH * 64) sp[tid] = part[tid];
    __syncthreads();
    if (tid == 0) {
        float raw[MPATH];
#pragma unroll
        for (int mm = 0; mm < MPATH; mm++) {
            float s = 0.f;
            for (int j = 0; j < nblk; j++) s += sp[mm * nblk + j];
            raw[mm] = s * (1.f / (float)NROW);
        }
        float mx = fmaxf(fmaxf(raw[0], raw[1]), fmaxf(raw[2], raw[3]));
        float e0 = expf(raw[0] - mx), e1 = expf(raw[1] - mx);
        float e2 = expf(raw[2] - mx), e3 = expf(raw[3] - mx);
        float dn = e0 + e1 + e2 + e3;
        sb[0] = e0 / dn; sb[1] = e1 / dn; sb[2] = e2 / dn; sb[3] = e3 / dn;
    }
    __syncthreads();

    const int i = blockIdx.x * 256 + tid;
    const int S = NROW * EDIM / 4;
    const float b0 = sb[0], b1 = sb[1], b2 = sb[2], b3 = sb[3];
    const float4* H4 = (const float4*)H;
    float4 h0 = H4[i], h1 = H4[i + S], h2 = H4[i + 2 * S], h3 = H4[i + 3 * S];
    float4 r;
    r.x = b0 * h0.x + b1 * h1.x + b2 * h2.x + b3 * h3.x;
    r.y = b0 * h0.y + b1 * h1.y + b2 * h2.y + b3 * h3.y;
    r.z = b0 * h0.z + b1 * h1.z + b2 * h2.z + b3 * h3.z;
    r.w = b0 * h0.w + b1 * h1.w + b2 * h2.w + b3 * h3.w;
    ((float4*)out)[i] = r;
    if (outh) {
        __nv_bfloat162 lo = __floats2bfloat162_rn(r.x, r.y);
        __nv_bfloat162 hi = __floats2bfloat162_rn(r.z, r.w);
        uint2 u;
        u.x = *reinterpret_cast<unsigned*>(&lo);
        u.y = *reinterpret_cast<unsigned*>(&hi);
        ((uint2*)outh)[i] = u;
    }
}

// fp32 -> bf16 shadow copy
__global__ void tobf16_k(const float* __restrict__ in, __nv_bfloat16* __restrict__ out)
{
    const int i = blockIdx.x * 256 + threadIdx.x;
    float4 v = ((const float4*)in)[i];
    __nv_bfloat162 lo = __floats2bfloat162_rn(v.x, v.y);
    __nv_bfloat162 hi = __floats2bfloat162_rn(v.z, v.w);
    uint2 u;
    u.x = *reinterpret_cast<unsigned*>(&lo);
    u.y = *reinterpret_cast<unsigned*>(&hi);
    ((uint2*)out)[i] = u;
}

extern "C" void kernel_launch(void* const* d_in, const int* in_sizes, int n_in,
                              void* d_out, int out_size)
{
    (void)in_sizes; (void)n_in; (void)out_size;

    const float* user    = (const float*)d_in[0];
    const float* product = (const float*)d_in[1];
    const float* V   = (const float*)d_in[2];
    const float* X   = (const float*)d_in[3];
    const float* Wp  = (const float*)d_in[4];
    const float* Bp  = (const float*)d_in[5];
    const float* Wq  = (const float*)d_in[6];
    const float* Bq  = (const float*)d_in[7];
    const float* Q   = (const float*)d_in[8];
    const int* unbrs = (const int*)d_in[9];
    const int* pnbrs = (const int*)d_in[10];
    float* out = (float*)d_out;

    float *dPS, *dH, *dPart;
    __nv_bfloat16 *dPNh, *dOtherh;
    cudaGetSymbolAddress((void**)&dPS,     g_PS);
    cudaGetSymbolAddress((void**)&dPNh,    g_PNh);
    cudaGetSymbolAddress((void**)&dOtherh, g_otherh);
    cudaGetSymbolAddress((void**)&dH,      g_H);
    cudaGetSymbolAddress((void**)&dPart,   g_part);

    cudaFuncSetAttribute(gemm_tc<0>, cudaFuncAttributeMaxDynamicSharedMemorySize, SMEM_BYTES);
    cudaFuncSetAttribute(gemm_tc<1>, cudaFuncAttributeMaxDynamicSharedMemorySize, SMEM_BYTES);

    // bf16 shadow of product for phase-0 gathers
    tobf16_k<<<NOTHER * EDIM / 4 / 256, 256>>>(product, dOtherh);

    for (int p = 0; p < 2; p++) {
        const float* src   = (p == 0) ? user    : product;
        const float* other = (p == 0) ? product : out;       // phase 2 attends over user_out
        const int*   nbrs  = (p == 0) ? unbrs   : pnbrs;
        const float* Vp  = V  + (size_t)p * MPATH * EDIM * DDIM;
        const float* Xp  = X  + (size_t)p * MPATH * DDIM;
        const float* Wpp = Wp + (size_t)p * MPATH * EDIM * DDIM;
        const float* Bpp = Bp + (size_t)p * MPATH * DDIM;
        const float* Wqp = Wq + (size_t)p * MPATH * EDIM * DDIM;
        const float* Bqp = Bq + (size_t)p * MPATH * DDIM;
        const float* Qp  = Q  + (size_t)p * MPATH * DDIM;
        float* outp = out + (size_t)p * NROW * EDIM;

        // PS = src@V (fp32, z=0) and PNh = bf16(other@W_p) (z=1) in ONE launch
        gemm_tc<0><<<dim3(NROW / 128, MPATH, 2), 256, SMEM_BYTES>>>(
            src, Vp, dPS, other, Wpp, dPNh, nullptr, nullptr, 0);
        attn_k<<<MPATH * NROW / 8, 256>>>(dPS, dPNh, Bpp, Xp, src, dOtherh, nbrs, dH);
        gemm_tc<1><<<dim3(NROW / 128, MPATH, 1), 256, SMEM_BYTES>>>(
            dH, Wqp, dPart, nullptr, nullptr, nullptr, Bqp, Qp, 1);
        combine_k<<<NROW * EDIM / 4 / 256, 256>>>(
            dH, dPart, NROW / 128, outp, (p == 0) ? dOtherh : nullptr);
    }
}

// round 8
// speedup vs baseline: 1.4597x; 1.0002x over previous
#include <cuda_runtime.h>
#include <cuda_bf16.h>
#include <mma.h>
#include <cstddef>

using namespace nvcuda;

#define NROW   8192
#define NOTHER 8192
#define EDIM   128
#define DDIM   64
#define KNBR   32
#define MPATH  4

#define LDA_H 136          // A smem stride (bf16 elems)
#define LDW_H 72           // W smem stride (bf16 elems)
#define LDC_F 68           // C staging stride (floats), aliases As
#define SMEM_BYTES (128 * LDA_H * 2 + 128 * LDW_H * 2)   // 34816 + 18432 = 53248

// Scratch (device globals: allocation-free rule)
__device__ float g_PS[(size_t)MPATH * NROW * DDIM];              // src @ V        (fp32)
__device__ __nv_bfloat16 g_PNh[(size_t)MPATH * NOTHER * DDIM];   // other @ W_p    (bf16)
__device__ __nv_bfloat16 g_otherh[(size_t)NOTHER * EDIM];        // bf16 shadow of gather target
__device__ float g_H [(size_t)MPATH * NROW * EDIM];              // H              (fp32)
__device__ float g_part[MPATH * 64];                             // sem partial sums

__device__ __forceinline__ float tanha(float x) {
    float y;
    asm("tanh.approx.f32 %0, %1;" : "=f"(y) : "f"(x));
    return y;
}
__device__ __forceinline__ __nv_bfloat162 bfc(unsigned u) {
    return *reinterpret_cast<__nv_bfloat162*>(&u);
}

// ---------------------------------------------------------------------------
// Tensor-core GEMM (bf16 wmma, m16n16k16). Per (m, row-tile): C = A @ W[m].
//   Block: 256 threads (8 warps). Tile: 128 rows x 64 cols, full K=128 in smem.
//   MODE 0, z=0: outF[m][n][d] = C            (fp32, PS path)
//   MODE 0, z=1: outH[m][n][d] = bf16(C)      (bf16, PN path; A1/W1 operands)
//   MODE 1:      outF[m*gridDim.x+bx] = sum_rows sum_d tanh(C+bias[m][d])*Qv[m][d]
// ---------------------------------------------------------------------------
template <int MODE>
__global__ void __launch_bounds__(256) gemm_tc(
    const float* __restrict__ A0, const float* __restrict__ W0, float* __restrict__ outF,
    const float* __restrict__ A1, const float* __restrict__ W1, __nv_bfloat16* __restrict__ outH,
    const float* __restrict__ bias, const float* __restrict__ Qv, int aPerM)
{
    extern __shared__ char smraw[];
    __nv_bfloat16* As = (__nv_bfloat16*)smraw;                    // [128][LDA_H]
    __nv_bfloat16* Ws = (__nv_bfloat16*)(smraw + 128 * LDA_H * 2); // [128][LDW_H]
    float* Cs = (float*)smraw;                                     // aliases As, [128][LDC_F]

    const int m  = blockIdx.y;
    const int n0 = blockIdx.x * 128;
    const int tid = threadIdx.x;
    const int wid = tid >> 5;
    const int z = (MODE == 0) ? blockIdx.z : 0;

    const float* A = (z == 1) ? A1 : A0;
    const float* W = ((z == 1) ? W1 : W0) + (size_t)m * EDIM * DDIM;
    if (aPerM) A += (size_t)m * NROW * EDIM;

    __shared__ float sB[DDIM], sQ[DDIM], red[8];
    if (MODE == 1 && tid < DDIM) {
        sB[tid] = bias[m * DDIM + tid];
        sQ[tid] = Qv[m * DDIM + tid];
    }

    // Load A tile (128x128 fp32) -> bf16 smem
#pragma unroll
    for (int i = 0; i < 16; i++) {
        int li = tid + i * 256;            // float4 index, 4096 total
        int r = li >> 5, c4 = (li & 31) << 2;
        float4 v = *(const float4*)(A + (size_t)(n0 + r) * EDIM + c4);
        __nv_bfloat162 lo = __floats2bfloat162_rn(v.x, v.y);
        __nv_bfloat162 hi = __floats2bfloat162_rn(v.z, v.w);
        *(__nv_bfloat162*)(As + r * LDA_H + c4)     = lo;
        *(__nv_bfloat162*)(As + r * LDA_H + c4 + 2) = hi;
    }
    // Load W (128x64 fp32) -> bf16 smem
#pragma unroll
    for (int i = 0; i < 8; i++) {
        int li = tid + i * 256;            // float4 index, 2048 total
        int r = li >> 4, c4 = (li & 15) << 2;
        float4 v = *(const float4*)(W + (size_t)r * DDIM + c4);
        __nv_bfloat162 lo = __floats2bfloat162_rn(v.x, v.y);
        __nv_bfloat162 hi = __floats2bfloat162_rn(v.z, v.w);
        *(__nv_bfloat162*)(Ws + r * LDW_H + c4)     = lo;
        *(__nv_bfloat162*)(Ws + r * LDW_H + c4 + 2) = hi;
    }
    __syncthreads();

    wmma::fragment<wmma::accumulator, 16, 16, 16, float> acc[4];
#pragma unroll
    for (int t = 0; t < 4; t++) wmma::fill_fragment(acc[t], 0.f);

    const int row0 = wid * 16;
#pragma unroll
    for (int k = 0; k < 8; k++) {
        wmma::fragment<wmma::matrix_a, 16, 16, 16, __nv_bfloat16, wmma::row_major> af;
        wmma::load_matrix_sync(af, As + row0 * LDA_H + k * 16, LDA_H);
#pragma unroll
        for (int t = 0; t < 4; t++) {
            wmma::fragment<wmma::matrix_b, 16, 16, 16, __nv_bfloat16, wmma::row_major> bf;
            wmma::load_matrix_sync(bf, Ws + (k * 16) * LDW_H + t * 16, LDW_H);
            wmma::mma_sync(acc[t], af, bf, acc[t]);
        }
    }

    if (MODE == 0 && z == 0) {
#pragma unroll
        for (int t = 0; t < 4; t++) {
            wmma::store_matrix_sync(
                outF + ((size_t)m * NROW + n0 + row0) * DDIM + t * 16,
                acc[t], DDIM, wmma::mem_row_major);
        }
    } else if (MODE == 0) {
        // bf16 output: stage fp32 C in smem (aliases As; MMA reads done), convert
        __syncthreads();
#pragma unroll
        for (int t = 0; t < 4; t++)
            wmma::store_matrix_sync(Cs + row0 * LDC_F + t * 16, acc[t], LDC_F, wmma::mem_row_major);
        __syncthreads();
#pragma unroll
        for (int i = 0; i < 16; i++) {
            int li = tid + i * 256;          // pair index over 4096 pairs
            int r = li >> 5, c2 = (li & 31) << 1;
            __nv_bfloat162 b = __floats2bfloat162_rn(Cs[r * LDC_F + c2], Cs[r * LDC_F + c2 + 1]);
            *(__nv_bfloat162*)(outH + ((size_t)m * NROW + n0 + r) * DDIM + c2) = b;
        }
    } else {
        __syncthreads();
#pragma unroll
        for (int t = 0; t < 4; t++)
            wmma::store_matrix_sync(Cs + row0 * LDC_F + t * 16, acc[t], LDC_F, wmma::mem_row_major);
        __syncthreads();

        float sv = 0.f;
#pragma unroll 4
        for (int li = tid; li < 128 * 64; li += 256) {
            int r = li >> 6, d = li & 63;
            sv += tanha(Cs[r * LDC_F + d] + sB[d]) * sQ[d];
        }
        sv += __shfl_xor_sync(0xffffffffu, sv, 16);
        sv += __shfl_xor_sync(0xffffffffu, sv, 8);
        sv += __shfl_xor_sync(0xffffffffu, sv, 4);
        sv += __shfl_xor_sync(0xffffffffu, sv, 2);
        sv += __shfl_xor_sync(0xffffffffu, sv, 1);
        if ((tid & 31) == 0) red[wid] = sv;
        __syncthreads();
        if (tid == 0) {
            float s = 0.f;
#pragma unroll
            for (int i = 0; i < 8; i++) s += red[i];
            outF[m * gridDim.x + blockIdx.x] = s;
        }
    }
}

// ---------------------------------------------------------------------------
// Attention + aggregation: one warp per (m, n). LANE-PER-K scores (no shuffle
// chains in the inner loop): lane k accumulates its neighbor's score over d,
// reading psb/x broadcast from smem and the PN row contiguously.
// ---------------------------------------------------------------------------
__global__ void __launch_bounds__(256) attn_k(
    const float* __restrict__ PS,
    const __nv_bfloat16* __restrict__ PNh,
    const float* __restrict__ Bp,     // [M][64]
    const float* __restrict__ X,      // [M][64]
    const float* __restrict__ src,    // [NROW][128]
    const __nv_bfloat16* __restrict__ otherh,  // [NOTHER][128] bf16
    const int*   __restrict__ nbrs,   // [M][NROW][K]
    float* __restrict__ H)
{
    __shared__ float s_psb[8][64];
    __shared__ float s_x[64];

    const int wid  = threadIdx.x >> 5;
    const int lane = threadIdx.x & 31;
    const int w = blockIdx.x * 8 + wid;
    const int m = w >> 13;                 // all warps in block share m
    const int n = w & (NROW - 1);
    const size_t base = (size_t)m * NROW + n;

    // stage psb (PS + Bp) per warp, x per block
    {
        float2 psv = *(const float2*)(PS + base * DDIM + 2 * lane);
        float2 bpv = *(const float2*)(Bp + m * DDIM + 2 * lane);
        s_psb[wid][2 * lane]     = psv.x + bpv.x;
        s_psb[wid][2 * lane + 1] = psv.y + bpv.y;
        if (wid == 0) {
            float2 xv = *(const float2*)(X + m * DDIM + 2 * lane);
            s_x[2 * lane]     = xv.x;
            s_x[2 * lane + 1] = xv.y;
        }
    }
    __syncthreads();

    const int myidx = nbrs[base * KNBR + lane];
    const __nv_bfloat16* pnrow = PNh + ((size_t)m * NOTHER + myidx) * DDIM;
    const float4* ppsb = (const float4*)s_psb[wid];
    const float4* px   = (const float4*)s_x;

    float sc = 0.f;
#pragma unroll
    for (int j = 0; j < 8; j++) {
        uint4 u = *(const uint4*)(pnrow + j * 8);
        __nv_bfloat162 p0 = bfc(u.x), p1 = bfc(u.y), p2 = bfc(u.z), p3 = bfc(u.w);
        float4 b0 = ppsb[j * 2], b1 = ppsb[j * 2 + 1];
        float4 x0 = px[j * 2],   x1 = px[j * 2 + 1];
        sc += tanha(b0.x + __low2float(p0))  * x0.x;
        sc += tanha(b0.y + __high2float(p0)) * x0.y;
        sc += tanha(b0.z + __low2float(p1))  * x0.z;
        sc += tanha(b0.w + __high2float(p1)) * x0.w;
        sc += tanha(b1.x + __low2float(p2))  * x1.x;
        sc += tanha(b1.y + __high2float(p2)) * x1.y;
        sc += tanha(b1.z + __low2float(p3))  * x1.z;
        sc += tanha(b1.w + __high2float(p3)) * x1.w;
    }

    // softmax over the full axis (lane holds score for its own k)
    const float baseline = (m == 0) ? -1e-9f : 1.220703125e-4f;  // 1/8192
    float mx = sc;
    mx = fmaxf(mx, __shfl_xor_sync(0xffffffffu, mx, 16));
    mx = fmaxf(mx, __shfl_xor_sync(0xffffffffu, mx, 8));
    mx = fmaxf(mx, __shfl_xor_sync(0xffffffffu, mx, 4));
    mx = fmaxf(mx, __shfl_xor_sync(0xffffffffu, mx, 2));
    mx = fmaxf(mx, __shfl_xor_sync(0xffffffffu, mx, 1));
    mx = fmaxf(mx, baseline);

    float e = __expf(sc - mx);
    float s = e;
    s += __shfl_xor_sync(0xffffffffu, s, 16);
    s += __shfl_xor_sync(0xffffffffu, s, 8);
    s += __shfl_xor_sync(0xffffffffu, s, 4);
    s += __shfl_xor_sync(0xffffffffu, s, 2);
    s += __shfl_xor_sync(0xffffffffu, s, 1);
    const float denom = s + (float)(NOTHER - KNBR) * __expf(baseline - mx);
    const float a = e / denom;   // lane k holds A_k

    // aggregation: lanes split the 128 dims (4 each), broadcast a/idx per k
    const float4* src4 = (const float4*)src;
    float4 acc = src4[(size_t)n * 32 + lane];
#pragma unroll
    for (int k = 0; k < KNBR; k++) {
        float ak = __shfl_sync(0xffffffffu, a, k);
        int idx  = __shfl_sync(0xffffffffu, myidx, k);
        uint2 u = *(const uint2*)(otherh + (size_t)idx * EDIM + lane * 4);
        __nv_bfloat162 v01 = bfc(u.x);
        __nv_bfloat162 v23 = bfc(u.y);
        acc.x += ak * __low2float(v01);
        acc.y += ak * __high2float(v01);
        acc.z += ak * __low2float(v23);
        acc.w += ak * __high2float(v23);
    }
    ((float4*)H)[base * 32 + lane] = acc;
}

// ---------------------------------------------------------------------------
// combine: beta = softmax_m(mean partials), out[n,e] = sum_m beta[m]*H[m,n,e].
// Optionally writes a bf16 shadow of out (for next phase's gathers).
// ---------------------------------------------------------------------------
__global__ void __launch_bounds__(256) combine_k(
    const float* __restrict__ H, const float* __restrict__ part, int nblk,
    float* __restrict__ out, __nv_bfloat16* __restrict__ outh)
{
    __shared__ float sp[256];
    __shared__ float sb[MPATH];
    const int tid = threadIdx.x;
    if (tid < MPATH * 64) sp[tid] = part[tid];
    __syncthreads();
    if (tid == 0) {
        float raw[MPATH];
#pragma unroll
        for (int mm = 0; mm < MPATH; mm++) {
            float s = 0.f;
            for (int j = 0; j < nblk; j++) s += sp[mm * nblk + j];
            raw[mm] = s * (1.f / (float)NROW);
        }
        float mx = fmaxf(fmaxf(raw[0], raw[1]), fmaxf(raw[2], raw[3]));
        float e0 = expf(raw[0] - mx), e1 = expf(raw[1] - mx);
        float e2 = expf(raw[2] - mx), e3 = expf(raw[3] - mx);
        float dn = e0 + e1 + e2 + e3;
        sb[0] = e0 / dn; sb[1] = e1 / dn; sb[2] = e2 / dn; sb[3] = e3 / dn;
    }
    __syncthreads();

    const int i = blockIdx.x * 256 + tid;
    const int S = NROW * EDIM / 4;
    const float b0 = sb[0], b1 = sb[1], b2 = sb[2], b3 = sb[3];
    const float4* H4 = (const float4*)H;
    float4 h0 = H4[i], h1 = H4[i + S], h2 = H4[i + 2 * S], h3 = H4[i + 3 * S];
    float4 r;
    r.x = b0 * h0.x + b1 * h1.x + b2 * h2.x + b3 * h3.x;
    r.y = b0 * h0.y + b1 * h1.y + b2 * h2.y + b3 * h3.y;
    r.z = b0 * h0.z + b1 * h1.z + b2 * h2.z + b3 * h3.z;
    r.w = b0 * h0.w + b1 * h1.w + b2 * h2.w + b3 * h3.w;
    ((float4*)out)[i] = r;
    if (outh) {
        __nv_bfloat162 lo = __floats2bfloat162_rn(r.x, r.y);
        __nv_bfloat162 hi = __floats2bfloat162_rn(r.z, r.w);
        uint2 u;
        u.x = *reinterpret_cast<unsigned*>(&lo);
        u.y = *reinterpret_cast<unsigned*>(&hi);
        ((uint2*)outh)[i] = u;
    }
}

// fp32 -> bf16 shadow copy
__global__ void tobf16_k(const float* __restrict__ in, __nv_bfloat16* __restrict__ out)
{
    const int i = blockIdx.x * 256 + threadIdx.x;
    float4 v = ((const float4*)in)[i];
    __nv_bfloat162 lo = __floats2bfloat162_rn(v.x, v.y);
    __nv_bfloat162 hi = __floats2bfloat162_rn(v.z, v.w);
    uint2 u;
    u.x = *reinterpret_cast<unsigned*>(&lo);
    u.y = *reinterpret_cast<unsigned*>(&hi);
    ((uint2*)out)[i] = u;
}

extern "C" void kernel_launch(void* const* d_in, const int* in_sizes, int n_in,
                              void* d_out, int out_size)
{
    (void)in_sizes; (void)n_in; (void)out_size;

    const float* user    = (const float*)d_in[0];
    const float* product = (const float*)d_in[1];
    const float* V   = (const float*)d_in[2];
    const float* X   = (const float*)d_in[3];
    const float* Wp  = (const float*)d_in[4];
    const float* Bp  = (const float*)d_in[5];
    const float* Wq  = (const float*)d_in[6];
    const float* Bq  = (const float*)d_in[7];
    const float* Q   = (const float*)d_in[8];
    const int* unbrs = (const int*)d_in[9];
    const int* pnbrs = (const int*)d_in[10];
    float* out = (float*)d_out;

    float *dPS, *dH, *dPart;
    __nv_bfloat16 *dPNh, *dOtherh;
    cudaGetSymbolAddress((void**)&dPS,     g_PS);
    cudaGetSymbolAddress((void**)&dPNh,    g_PNh);
    cudaGetSymbolAddress((void**)&dOtherh, g_otherh);
    cudaGetSymbolAddress((void**)&dH,      g_H);
    cudaGetSymbolAddress((void**)&dPart,   g_part);

    cudaFuncSetAttribute(gemm_tc<0>, cudaFuncAttributeMaxDynamicSharedMemorySize, SMEM_BYTES);
    cudaFuncSetAttribute(gemm_tc<1>, cudaFuncAttributeMaxDynamicSharedMemorySize, SMEM_BYTES);

    // bf16 shadow of product for phase-0 gathers
    tobf16_k<<<NOTHER * EDIM / 4 / 256, 256>>>(product, dOtherh);

    for (int p = 0; p < 2; p++) {
        const float* src   = (p == 0) ? user    : product;
        const float* other = (p == 0) ? product : out;       // phase 2 attends over user_out
        const int*   nbrs  = (p == 0) ? unbrs   : pnbrs;
        const float* Vp  = V  + (size_t)p * MPATH * EDIM * DDIM;
        const float* Xp  = X  + (size_t)p * MPATH * DDIM;
        const float* Wpp = Wp + (size_t)p * MPATH * EDIM * DDIM;
        const float* Bpp = Bp + (size_t)p * MPATH * DDIM;
        const float* Wqp = Wq + (size_t)p * MPATH * EDIM * DDIM;
        const float* Bqp = Bq + (size_t)p * MPATH * DDIM;
        const float* Qp  = Q  + (size_t)p * MPATH * DDIM;
        float* outp = out + (size_t)p * NROW * EDIM;

        // PS = src@V (fp32, z=0) and PNh = bf16(other@W_p) (z=1) in ONE launch
        gemm_tc<0><<<dim3(NROW / 128, MPATH, 2), 256, SMEM_BYTES>>>(
            src, Vp, dPS, other, Wpp, dPNh, nullptr, nullptr, 0);
        attn_k<<<MPATH * NROW / 8, 256>>>(dPS, dPNh, Bpp, Xp, src, dOtherh, nbrs, dH);
        gemm_tc<1><<<dim3(NROW / 128, MPATH, 1), 256, SMEM_BYTES>>>(
            dH, Wqp, dPart, nullptr, nullptr, nullptr, Bqp, Qp, 1);
        combine_k<<<NROW * EDIM / 4 / 256, 256>>>(
            dH, dPart, NROW / 128, outp, (p == 0) ? dOtherh : nullptr);
    }
}

// round 9
// speedup vs baseline: 1.8710x; 1.2818x over previous
#include <cuda_runtime.h>
#include <cuda_bf16.h>
#include <cuda_fp8.h>
#include <cuda_fp16.h>
#include <mma.h>
#include <cstddef>

using namespace nvcuda;

#define NROW   8192
#define NOTHER 8192
#define EDIM   128
#define DDIM   64
#define KNBR   32
#define MPATH  4

#define LDA_H 136          // A smem stride (bf16 elems), 64 rows
#define LDW_H 72           // W smem stride (bf16 elems), 128 rows
#define LDC_F 68           // C staging stride (floats), aliases As
#define SMEM_BYTES (64 * LDA_H * 2 + 128 * LDW_H * 2)   // 17408 + 18432 = 35840

// Scratch (device globals: allocation-free rule)
__device__ float g_PS[(size_t)MPATH * NROW * DDIM];            // src @ V      (fp32)
__device__ unsigned char g_PN8[(size_t)MPATH * NOTHER * DDIM]; // other @ W_p  (fp8 e4m3)
__device__ unsigned char g_oth8[(size_t)NOTHER * EDIM];        // fp8 shadow of gather target
__device__ float g_H [(size_t)MPATH * NROW * EDIM];            // H            (fp32)
__device__ float g_part[MPATH * 128];                          // sem partial sums

__device__ __forceinline__ float tanha(float x) {
    float y;
    asm("tanh.approx.f32 %0, %1;" : "=f"(y) : "f"(x));
    return y;
}
__device__ __forceinline__ __half2 tanh2(__half2 x) {
    unsigned xi = *reinterpret_cast<unsigned*>(&x), yi;
    asm("tanh.approx.f16x2 %0, %1;" : "=r"(yi) : "r"(xi));
    return *reinterpret_cast<__half2*>(&yi);
}
__device__ __forceinline__ __half2 f8x2h2(unsigned v) {
    __half2_raw r = __nv_cvt_fp8x2_to_halfraw2((__nv_fp8x2_storage_t)(v & 0xffffu), __NV_E4M3);
    return *reinterpret_cast<__half2*>(&r);
}
__device__ __forceinline__ unsigned f2f8(float a, float b) {
    return (unsigned)__nv_cvt_float2_to_fp8x2(make_float2(a, b), __NV_SATFINITE, __NV_E4M3);
}

// ---------------------------------------------------------------------------
// Tensor-core GEMM (bf16 wmma, m16n16k16). Per (m, 64-row tile): C = A @ W[m].
//   Block: 256 threads (8 warps = 4 row-chunks x 2 col-halves). K=128 in smem.
//   MODE 0, z=0: outF[m][n][d] = C            (fp32, PS path)
//   MODE 0, z=1: outQ[m][n][d] = fp8(C)       (PN path; A1/W1 operands)
//   MODE 1:      outF[m*gridDim.x+bx] = sum_rows sum_d tanh(C+bias[m][d])*Qv[m][d]
// ---------------------------------------------------------------------------
template <int MODE>
__global__ void __launch_bounds__(256) gemm_tc(
    const float* __restrict__ A0, const float* __restrict__ W0, float* __restrict__ outF,
    const float* __restrict__ A1, const float* __restrict__ W1, unsigned char* __restrict__ outQ,
    const float* __restrict__ bias, const float* __restrict__ Qv, int aPerM)
{
    extern __shared__ char smraw[];
    __nv_bfloat16* As = (__nv_bfloat16*)smraw;                     // [64][LDA_H]
    __nv_bfloat16* Ws = (__nv_bfloat16*)(smraw + 64 * LDA_H * 2);  // [128][LDW_H]
    float* Cs = (float*)smraw;                                     // aliases As, [64][LDC_F]

    const int m  = blockIdx.y;
    const int n0 = blockIdx.x * 64;
    const int tid = threadIdx.x;
    const int wid = tid >> 5;
    const int z = (MODE == 0) ? blockIdx.z : 0;

    const float* A = (z == 1) ? A1 : A0;
    const float* W = ((z == 1) ? W1 : W0) + (size_t)m * EDIM * DDIM;
    if (aPerM) A += (size_t)m * NROW * EDIM;

    __shared__ float sB[DDIM], sQ[DDIM], red[8];
    if (MODE == 1 && tid < DDIM) {
        sB[tid] = bias[m * DDIM + tid];
        sQ[tid] = Qv[m * DDIM + tid];
    }

    // Load A tile (64x128 fp32) -> bf16 smem
#pragma unroll
    for (int i = 0; i < 8; i++) {
        int li = tid + i * 256;            // float4 index, 2048 total
        int r = li >> 5, c4 = (li & 31) << 2;
        float4 v = *(const float4*)(A + (size_t)(n0 + r) * EDIM + c4);
        *(__nv_bfloat162*)(As + r * LDA_H + c4)     = __floats2bfloat162_rn(v.x, v.y);
        *(__nv_bfloat162*)(As + r * LDA_H + c4 + 2) = __floats2bfloat162_rn(v.z, v.w);
    }
    // Load W (128x64 fp32) -> bf16 smem
#pragma unroll
    for (int i = 0; i < 8; i++) {
        int li = tid + i * 256;            // float4 index, 2048 total
        int r = li >> 4, c4 = (li & 15) << 2;
        float4 v = *(const float4*)(W + (size_t)r * DDIM + c4);
        *(__nv_bfloat162*)(Ws + r * LDW_H + c4)     = __floats2bfloat162_rn(v.x, v.y);
        *(__nv_bfloat162*)(Ws + r * LDW_H + c4 + 2) = __floats2bfloat162_rn(v.z, v.w);
    }
    __syncthreads();

    const int row0 = (wid >> 1) * 16;      // 4 row-chunks of 16
    const int col0 = (wid & 1) * 32;       // 2 col-halves of 32

    wmma::fragment<wmma::accumulator, 16, 16, 16, float> acc[2];
#pragma unroll
    for (int t = 0; t < 2; t++) wmma::fill_fragment(acc[t], 0.f);

#pragma unroll
    for (int k = 0; k < 8; k++) {
        wmma::fragment<wmma::matrix_a, 16, 16, 16, __nv_bfloat16, wmma::row_major> af;
        wmma::load_matrix_sync(af, As + row0 * LDA_H + k * 16, LDA_H);
#pragma unroll
        for (int t = 0; t < 2; t++) {
            wmma::fragment<wmma::matrix_b, 16, 16, 16, __nv_bfloat16, wmma::row_major> bf;
            wmma::load_matrix_sync(bf, Ws + (k * 16) * LDW_H + col0 + t * 16, LDW_H);
            wmma::mma_sync(acc[t], af, bf, acc[t]);
        }
    }

    if (MODE == 0 && z == 0) {
#pragma unroll
        for (int t = 0; t < 2; t++) {
            wmma::store_matrix_sync(
                outF + ((size_t)m * NROW + n0 + row0) * DDIM + col0 + t * 16,
                acc[t], DDIM, wmma::mem_row_major);
        }
    } else if (MODE == 0) {
        // fp8 output: stage fp32 C in smem (aliases As; MMA reads done), convert
        __syncthreads();
#pragma unroll
        for (int t = 0; t < 2; t++)
            wmma::store_matrix_sync(Cs + row0 * LDC_F + col0 + t * 16, acc[t], LDC_F, wmma::mem_row_major);
        __syncthreads();
#pragma unroll
        for (int i = 0; i < 4; i++) {
            int li = tid + i * 256;          // 4-dim group index, 1024 total
            int r = li >> 4, g = li & 15;
            const float* c = Cs + r * LDC_F + g * 4;
            unsigned u = f2f8(c[0], c[1]) | (f2f8(c[2], c[3]) << 16);
            ((unsigned*)(outQ + ((size_t)m * NROW + n0 + r) * DDIM))[g] = u;
        }
    } else {
        __syncthreads();
#pragma unroll
        for (int t = 0; t < 2; t++)
            wmma::store_matrix_sync(Cs + row0 * LDC_F + col0 + t * 16, acc[t], LDC_F, wmma::mem_row_major);
        __syncthreads();

        float sv = 0.f;
#pragma unroll 4
        for (int li = tid; li < 64 * 64; li += 256) {
            int r = li >> 6, d = li & 63;
            sv += tanha(Cs[r * LDC_F + d] + sB[d]) * sQ[d];
        }
        sv += __shfl_xor_sync(0xffffffffu, sv, 16);
        sv += __shfl_xor_sync(0xffffffffu, sv, 8);
        sv += __shfl_xor_sync(0xffffffffu, sv, 4);
        sv += __shfl_xor_sync(0xffffffffu, sv, 2);
        sv += __shfl_xor_sync(0xffffffffu, sv, 1);
        if ((tid & 31) == 0) red[wid] = sv;
        __syncthreads();
        if (tid == 0) {
            float s = 0.f;
#pragma unroll
            for (int i = 0; i < 8; i++) s += red[i];
            outF[m * gridDim.x + blockIdx.x] = s;
        }
    }
}

// ---------------------------------------------------------------------------
// Attention + aggregation: one warp per (m, n). Lane-per-k scores in packed
// f16x2 (fp8 PN rows, tanh.approx.f16x2); fp8 aggregation gathers; fp32 H.
// ---------------------------------------------------------------------------
__global__ void __launch_bounds__(256) attn_k(
    const float* __restrict__ PS,
    const unsigned char* __restrict__ PN8,     // [M][NOTHER][64] fp8
    const float* __restrict__ Bp,              // [M][64]
    const float* __restrict__ X,               // [M][64]
    const float* __restrict__ src,             // [NROW][128] fp32
    const unsigned char* __restrict__ oth8,    // [NOTHER][128] fp8
    const int*   __restrict__ nbrs,            // [M][NROW][K]
    float* __restrict__ H)
{
    __shared__ __half2 s_psb[8][32];
    __shared__ __half2 s_x[32];

    const int wid  = threadIdx.x >> 5;
    const int lane = threadIdx.x & 31;
    const int w = blockIdx.x * 8 + wid;
    const int m = w >> 13;
    const int n = w & (NROW - 1);
    const size_t base = (size_t)m * NROW + n;

    {
        float2 psv = *(const float2*)(PS + base * DDIM + 2 * lane);
        float2 bpv = *(const float2*)(Bp + m * DDIM + 2 * lane);
        s_psb[wid][lane] = __floats2half2_rn(psv.x + bpv.x, psv.y + bpv.y);
        if (wid == 0) {
            float2 xv = *(const float2*)(X + m * DDIM + 2 * lane);
            s_x[lane] = __floats2half2_rn(xv.x, xv.y);
        }
    }
    __syncthreads();

    const int myidx = nbrs[base * KNBR + lane];
    const uint4* pn4 = (const uint4*)(PN8 + ((size_t)m * NOTHER + myidx) * DDIM);
    const __half2* psb = s_psb[wid];

    __half2 a2 = __floats2half2_rn(0.f, 0.f);
#pragma unroll
    for (int j = 0; j < 4; j++) {
        uint4 u = pn4[j];
        const int pb = j * 8;
#define PW(word, pi) { \
        __half2 plo = f8x2h2(word); \
        __half2 phi = f8x2h2((word) >> 16); \
        a2 = __hfma2(tanh2(__hadd2(psb[pi], plo)),     s_x[pi],     a2); \
        a2 = __hfma2(tanh2(__hadd2(psb[(pi)+1], phi)), s_x[(pi)+1], a2); }
        PW(u.x, pb); PW(u.y, pb + 2); PW(u.z, pb + 4); PW(u.w, pb + 6);
#undef PW
    }
    float sc = __low2float(a2) + __high2float(a2);

    // softmax over the full axis (lane holds score for its own k)
    const float baseline = (m == 0) ? -1e-9f : 1.220703125e-4f;  // 1/8192
    float mx = sc;
    mx = fmaxf(mx, __shfl_xor_sync(0xffffffffu, mx, 16));
    mx = fmaxf(mx, __shfl_xor_sync(0xffffffffu, mx, 8));
    mx = fmaxf(mx, __shfl_xor_sync(0xffffffffu, mx, 4));
    mx = fmaxf(mx, __shfl_xor_sync(0xffffffffu, mx, 2));
    mx = fmaxf(mx, __shfl_xor_sync(0xffffffffu, mx, 1));
    mx = fmaxf(mx, baseline);

    float e = __expf(sc - mx);
    float s = e;
    s += __shfl_xor_sync(0xffffffffu, s, 16);
    s += __shfl_xor_sync(0xffffffffu, s, 8);
    s += __shfl_xor_sync(0xffffffffu, s, 4);
    s += __shfl_xor_sync(0xffffffffu, s, 2);
    s += __shfl_xor_sync(0xffffffffu, s, 1);
    const float denom = s + (float)(NOTHER - KNBR) * __expf(baseline - mx);
    const float a = e / denom;   // lane k holds A_k

    // aggregation: lanes split the 128 dims (4 each), broadcast a/idx per k
    const float4* src4 = (const float4*)src;
    float4 acc = src4[(size_t)n * 32 + lane];
#pragma unroll
    for (int k = 0; k < KNBR; k++) {
        float ak = __shfl_sync(0xffffffffu, a, k);
        int idx  = __shfl_sync(0xffffffffu, myidx, k);
        unsigned u = ((const unsigned*)(oth8 + (size_t)idx * EDIM))[lane];
        float2 f01 = __half22float2(f8x2h2(u));
        float2 f23 = __half22float2(f8x2h2(u >> 16));
        acc.x += ak * f01.x;
        acc.y += ak * f01.y;
        acc.z += ak * f23.x;
        acc.w += ak * f23.y;
    }
    ((float4*)H)[base * 32 + lane] = acc;
}

// ---------------------------------------------------------------------------
// combine: beta = softmax_m(mean partials), out[n,e] = sum_m beta[m]*H[m,n,e].
// Optionally writes an fp8 shadow of out (for next phase's gathers).
// ---------------------------------------------------------------------------
__global__ void __launch_bounds__(256) combine_k(
    const float* __restrict__ H, const float* __restrict__ part, int nblk,
    float* __restrict__ out, unsigned char* __restrict__ outq)
{
    __shared__ float sp[MPATH * 128];
    __shared__ float raws[MPATH];
    __shared__ float sb[MPATH];
    const int tid = threadIdx.x;
    const int wid = tid >> 5;
    const int lane = tid & 31;
    for (int j = tid; j < MPATH * 128; j += 256) sp[j] = part[j];
    __syncthreads();
    if (wid < MPATH) {
        float s = 0.f;
        for (int j = lane; j < nblk; j += 32) s += sp[wid * 128 + j];
        s += __shfl_xor_sync(0xffffffffu, s, 16);
        s += __shfl_xor_sync(0xffffffffu, s, 8);
        s += __shfl_xor_sync(0xffffffffu, s, 4);
        s += __shfl_xor_sync(0xffffffffu, s, 2);
        s += __shfl_xor_sync(0xffffffffu, s, 1);
        if (lane == 0) raws[wid] = s * (1.f / (float)NROW);
    }
    __syncthreads();
    if (tid == 0) {
        float mx = fmaxf(fmaxf(raws[0], raws[1]), fmaxf(raws[2], raws[3]));
        float e0 = expf(raws[0] - mx), e1 = expf(raws[1] - mx);
        float e2 = expf(raws[2] - mx), e3 = expf(raws[3] - mx);
        float dn = e0 + e1 + e2 + e3;
        sb[0] = e0 / dn; sb[1] = e1 / dn; sb[2] = e2 / dn; sb[3] = e3 / dn;
    }
    __syncthreads();

    const int i = blockIdx.x * 256 + tid;
    const int S = NROW * EDIM / 4;
    const float b0 = sb[0], b1 = sb[1], b2 = sb[2], b3 = sb[3];
    const float4* H4 = (const float4*)H;
    float4 h0 = H4[i], h1 = H4[i + S], h2 = H4[i + 2 * S], h3 = H4[i + 3 * S];
    float4 r;
    r.x = b0 * h0.x + b1 * h1.x + b2 * h2.x + b3 * h3.x;
    r.y = b0 * h0.y + b1 * h1.y + b2 * h2.y + b3 * h3.y;
    r.z = b0 * h0.z + b1 * h1.z + b2 * h2.z + b3 * h3.z;
    r.w = b0 * h0.w + b1 * h1.w + b2 * h2.w + b3 * h3.w;
    ((float4*)out)[i] = r;
    if (outq) {
        unsigned u = f2f8(r.x, r.y) | (f2f8(r.z, r.w) << 16);
        ((unsigned*)outq)[i] = u;
    }
}

// fp32 -> fp8 shadow copy
__global__ void tofp8_k(const float* __restrict__ in, unsigned char* __restrict__ out)
{
    const int i = blockIdx.x * 256 + threadIdx.x;
    float4 v = ((const float4*)in)[i];
    unsigned u = f2f8(v.x, v.y) | (f2f8(v.z, v.w) << 16);
    ((unsigned*)out)[i] = u;
}

extern "C" void kernel_launch(void* const* d_in, const int* in_sizes, int n_in,
                              void* d_out, int out_size)
{
    (void)in_sizes; (void)n_in; (void)out_size;

    const float* user    = (const float*)d_in[0];
    const float* product = (const float*)d_in[1];
    const float* V   = (const float*)d_in[2];
    const float* X   = (const float*)d_in[3];
    const float* Wp  = (const float*)d_in[4];
    const float* Bp  = (const float*)d_in[5];
    const float* Wq  = (const float*)d_in[6];
    const float* Bq  = (const float*)d_in[7];
    const float* Q   = (const float*)d_in[8];
    const int* unbrs = (const int*)d_in[9];
    const int* pnbrs = (const int*)d_in[10];
    float* out = (float*)d_out;

    float *dPS, *dH, *dPart;
    unsigned char *dPN8, *dOth8;
    cudaGetSymbolAddress((void**)&dPS,   g_PS);
    cudaGetSymbolAddress((void**)&dPN8,  g_PN8);
    cudaGetSymbolAddress((void**)&dOth8, g_oth8);
    cudaGetSymbolAddress((void**)&dH,    g_H);
    cudaGetSymbolAddress((void**)&dPart, g_part);

    cudaFuncSetAttribute(gemm_tc<0>, cudaFuncAttributeMaxDynamicSharedMemorySize, SMEM_BYTES);
    cudaFuncSetAttribute(gemm_tc<1>, cudaFuncAttributeMaxDynamicSharedMemorySize, SMEM_BYTES);

    // fp8 shadow of product for phase-0 gathers
    tofp8_k<<<NOTHER * EDIM / 4 / 256, 256>>>(product, dOth8);

    for (int p = 0; p < 2; p++) {
        const float* src   = (p == 0) ? user    : product;
        const float* other = (p == 0) ? product : out;       // phase 2 attends over user_out
        const int*   nbrs  = (p == 0) ? unbrs   : pnbrs;
        const float* Vp  = V  + (size_t)p * MPATH * EDIM * DDIM;
        const float* Xp  = X  + (size_t)p * MPATH * DDIM;
        const float* Wpp = Wp + (size_t)p * MPATH * EDIM * DDIM;
        const float* Bpp = Bp + (size_t)p * MPATH * DDIM;
        const float* Wqp = Wq + (size_t)p * MPATH * EDIM * DDIM;
        const float* Bqp = Bq + (size_t)p * MPATH * DDIM;
        const float* Qp  = Q  + (size_t)p * MPATH * DDIM;
        float* outp = out + (size_t)p * NROW * EDIM;

        // PS = src@V (fp32, z=0) and PN8 = fp8(other@W_p) (z=1) in ONE launch
        gemm_tc<0><<<dim3(NROW / 64, MPATH, 2), 256, SMEM_BYTES>>>(
            src, Vp, dPS, other, Wpp, dPN8, nullptr, nullptr, 0);
        attn_k<<<MPATH * NROW / 8, 256>>>(dPS, dPN8, Bpp, Xp, src, dOth8, nbrs, dH);
        gemm_tc<1><<<dim3(NROW / 64, MPATH, 1), 256, SMEM_BYTES>>>(
            dH, Wqp, dPart, nullptr, nullptr, nullptr, Bqp, Qp, 1);
        combine_k<<<NROW * EDIM / 4 / 256, 256>>>(
            dH, dPart, NROW / 64, outp, (p == 0) ? dOth8 : nullptr);
    }
}

// round 10
// speedup vs baseline: 1.8953x; 1.0130x over previous
#include <cuda_runtime.h>
#include <cuda_bf16.h>
#include <cuda_fp8.h>
#include <cuda_fp16.h>
#include <mma.h>
#include <cstddef>

using namespace nvcuda;

#define NROW   8192
#define NOTHER 8192
#define EDIM   128
#define DDIM   64
#define KNBR   32
#define MPATH  4

#define LDA_H 136          // A smem stride (bf16 elems), 64 rows
#define LDW_H 72           // W smem stride (bf16 elems), 128 rows
#define LDC_F 68           // C staging stride (floats), aliases As
#define SMEM_BYTES (64 * LDA_H * 2 + 128 * LDW_H * 2)   // 17408 + 18432 = 35840

// Scratch (device globals: allocation-free rule)
__device__ __half g_PSh[(size_t)MPATH * NROW * DDIM];          // src@V + Bp   (fp16)
__device__ unsigned char g_PN8[(size_t)MPATH * NOTHER * DDIM]; // other @ W_p  (fp8 e4m3)
__device__ unsigned char g_oth8[(size_t)NOTHER * EDIM];        // fp8 shadow of gather target
__device__ float g_H [(size_t)MPATH * NROW * EDIM];            // H            (fp32)
__device__ __nv_bfloat16 g_Hh[(size_t)MPATH * NROW * EDIM];    // H            (bf16, for sem GEMM)
__device__ float g_part[MPATH * 128];                          // sem partial sums

__device__ __forceinline__ float tanha(float x) {
    float y;
    asm("tanh.approx.f32 %0, %1;" : "=f"(y) : "f"(x));
    return y;
}
__device__ __forceinline__ __half2 tanh2(__half2 x) {
    unsigned xi = *reinterpret_cast<unsigned*>(&x), yi;
    asm("tanh.approx.f16x2 %0, %1;" : "=r"(yi) : "r"(xi));
    return *reinterpret_cast<__half2*>(&yi);
}
__device__ __forceinline__ __half2 f8x2h2(unsigned v) {
    __half2_raw r = __nv_cvt_fp8x2_to_halfraw2((__nv_fp8x2_storage_t)(v & 0xffffu), __NV_E4M3);
    return *reinterpret_cast<__half2*>(&r);
}
__device__ __forceinline__ unsigned f2f8(float a, float b) {
    return (unsigned)__nv_cvt_float2_to_fp8x2(make_float2(a, b), __NV_SATFINITE, __NV_E4M3);
}

// ---------------------------------------------------------------------------
// Tensor-core GEMM (bf16 wmma, m16n16k16). Per (m, 64-row tile): C = A @ W[m].
//   Block: 256 threads (8 warps = 4 row-chunks x 2 col-halves). K=128 in smem.
//   MODE 0, z=0: outP[m][n][d] = fp16(C + bias[m][d])     (PS path, Bp folded)
//   MODE 0, z=1: outQ[m][n][d] = fp8(C)                   (PN path; A1/W1)
//   MODE 1:      outF[m*gridDim.x+bx] = sum_rows sum_d tanh(C+bias)*Qv[m][d]
//                (A read from bf16 Ah)
// ---------------------------------------------------------------------------
template <int MODE>
__global__ void __launch_bounds__(256) gemm_tc(
    const float* __restrict__ A0, const float* __restrict__ W0, __half* __restrict__ outP,
    const float* __restrict__ A1, const float* __restrict__ W1, unsigned char* __restrict__ outQ,
    const __nv_bfloat16* __restrict__ Ah, float* __restrict__ outF,
    const float* __restrict__ bias, const float* __restrict__ Qv, int aPerM)
{
    extern __shared__ char smraw[];
    __nv_bfloat16* As = (__nv_bfloat16*)smraw;                     // [64][LDA_H]
    __nv_bfloat16* Ws = (__nv_bfloat16*)(smraw + 64 * LDA_H * 2);  // [128][LDW_H]
    float* Cs = (float*)smraw;                                     // aliases As, [64][LDC_F]

    const int m  = blockIdx.y;
    const int n0 = blockIdx.x * 64;
    const int tid = threadIdx.x;
    const int wid = tid >> 5;
    const int z = (MODE == 0) ? blockIdx.z : 0;

    const float* W = ((MODE == 0 && z == 1) ? W1 : W0) + (size_t)m * EDIM * DDIM;

    __shared__ float sB[DDIM], sQ[DDIM], red[8];
    if ((MODE == 1 || z == 0) && tid < DDIM) {
        sB[tid] = bias[m * DDIM + tid];
        if (MODE == 1) sQ[tid] = Qv[m * DDIM + tid];
    }

    // Load A tile (64x128) -> bf16 smem
    if (MODE == 1) {
        const __nv_bfloat16* Ap = Ah + (aPerM ? (size_t)m * NROW * EDIM : 0);
#pragma unroll
        for (int i = 0; i < 4; i++) {
            int li = tid + i * 256;            // uint4 index, 1024 total
            int r = li >> 4, c8 = (li & 15) << 3;
            *(uint4*)(As + r * LDA_H + c8) =
                *(const uint4*)(Ap + (size_t)(n0 + r) * EDIM + c8);
        }
    } else {
        const float* A = (z == 1) ? A1 : A0;
        if (aPerM) A += (size_t)m * NROW * EDIM;
#pragma unroll
        for (int i = 0; i < 8; i++) {
            int li = tid + i * 256;            // float4 index, 2048 total
            int r = li >> 5, c4 = (li & 31) << 2;
            float4 v = *(const float4*)(A + (size_t)(n0 + r) * EDIM + c4);
            *(__nv_bfloat162*)(As + r * LDA_H + c4)     = __floats2bfloat162_rn(v.x, v.y);
            *(__nv_bfloat162*)(As + r * LDA_H + c4 + 2) = __floats2bfloat162_rn(v.z, v.w);
        }
    }
    // Load W (128x64 fp32) -> bf16 smem
#pragma unroll
    for (int i = 0; i < 8; i++) {
        int li = tid + i * 256;            // float4 index, 2048 total
        int r = li >> 4, c4 = (li & 15) << 2;
        float4 v = *(const float4*)(W + (size_t)r * DDIM + c4);
        *(__nv_bfloat162*)(Ws + r * LDW_H + c4)     = __floats2bfloat162_rn(v.x, v.y);
        *(__nv_bfloat162*)(Ws + r * LDW_H + c4 + 2) = __floats2bfloat162_rn(v.z, v.w);
    }
    __syncthreads();

    const int row0 = (wid >> 1) * 16;      // 4 row-chunks of 16
    const int col0 = (wid & 1) * 32;       // 2 col-halves of 32

    wmma::fragment<wmma::accumulator, 16, 16, 16, float> acc[2];
#pragma unroll
    for (int t = 0; t < 2; t++) wmma::fill_fragment(acc[t], 0.f);

#pragma unroll
    for (int k = 0; k < 8; k++) {
        wmma::fragment<wmma::matrix_a, 16, 16, 16, __nv_bfloat16, wmma::row_major> af;
        wmma::load_matrix_sync(af, As + row0 * LDA_H + k * 16, LDA_H);
#pragma unroll
        for (int t = 0; t < 2; t++) {
            wmma::fragment<wmma::matrix_b, 16, 16, 16, __nv_bfloat16, wmma::row_major> bf;
            wmma::load_matrix_sync(bf, Ws + (k * 16) * LDW_H + col0 + t * 16, LDW_H);
            wmma::mma_sync(acc[t], af, bf, acc[t]);
        }
    }

    // Stage fp32 C in smem (aliases As; A reads complete after the MMA loop)
    __syncthreads();
#pragma unroll
    for (int t = 0; t < 2; t++)
        wmma::store_matrix_sync(Cs + row0 * LDC_F + col0 + t * 16, acc[t], LDC_F, wmma::mem_row_major);
    __syncthreads();

    if (MODE == 0 && z == 0) {
        // fp16 output with bias folded
#pragma unroll
        for (int i = 0; i < 8; i++) {
            int li = tid + i * 256;          // half2 index, 2048 total
            int r = li >> 5, c2 = (li & 31) << 1;
            __half2 h = __floats2half2_rn(Cs[r * LDC_F + c2]     + sB[c2],
                                          Cs[r * LDC_F + c2 + 1] + sB[c2 + 1]);
            *(__half2*)(outP + ((size_t)m * NROW + n0 + r) * DDIM + c2) = h;
        }
    } else if (MODE == 0) {
        // fp8 output
#pragma unroll
        for (int i = 0; i < 4; i++) {
            int li = tid + i * 256;          // 4-dim group index, 1024 total
            int r = li >> 4, g = li & 15;
            const float* c = Cs + r * LDC_F + g * 4;
            unsigned u = f2f8(c[0], c[1]) | (f2f8(c[2], c[3]) << 16);
            ((unsigned*)(outQ + ((size_t)m * NROW + n0 + r) * DDIM))[g] = u;
        }
    } else {
        float sv = 0.f;
#pragma unroll 4
        for (int li = tid; li < 64 * 64; li += 256) {
            int r = li >> 6, d = li & 63;
            sv += tanha(Cs[r * LDC_F + d] + sB[d]) * sQ[d];
        }
        sv += __shfl_xor_sync(0xffffffffu, sv, 16);
        sv += __shfl_xor_sync(0xffffffffu, sv, 8);
        sv += __shfl_xor_sync(0xffffffffu, sv, 4);
        sv += __shfl_xor_sync(0xffffffffu, sv, 2);
        sv += __shfl_xor_sync(0xffffffffu, sv, 1);
        if ((tid & 31) == 0) red[wid] = sv;
        __syncthreads();
        if (tid == 0) {
            float s = 0.f;
#pragma unroll
            for (int i = 0; i < 8; i++) s += red[i];
            outF[m * gridDim.x + blockIdx.x] = s;
        }
    }
}

// ---------------------------------------------------------------------------
// Attention + aggregation: one warp per (m, n). Lane-per-k scores in packed
// f16x2 (fp8 PN rows, fp16 PS with Bp pre-folded); fp8 aggregation gathers;
// H written fp32 (combine) + bf16 (sem GEMM).
// ---------------------------------------------------------------------------
__global__ void __launch_bounds__(256) attn_k(
    const __half* __restrict__ PSh,            // [M][NROW][64] fp16, Bp folded
    const unsigned char* __restrict__ PN8,     // [M][NOTHER][64] fp8
    const float* __restrict__ X,               // [M][64]
    const float* __restrict__ src,             // [NROW][128] fp32
    const unsigned char* __restrict__ oth8,    // [NOTHER][128] fp8
    const int*   __restrict__ nbrs,            // [M][NROW][K]
    float* __restrict__ H,
    __nv_bfloat16* __restrict__ Hh)
{
    __shared__ __half2 s_psb[8][32];
    __shared__ __half2 s_x[32];

    const int wid  = threadIdx.x >> 5;
    const int lane = threadIdx.x & 31;
    const int w = blockIdx.x * 8 + wid;
    const int m = w >> 13;
    const int n = w & (NROW - 1);
    const size_t base = (size_t)m * NROW + n;

    s_psb[wid][lane] = ((const __half2*)(PSh + base * DDIM))[lane];
    if (wid == 0) {
        float2 xv = *(const float2*)(X + m * DDIM + 2 * lane);
        s_x[lane] = __floats2half2_rn(xv.x, xv.y);
    }
    __syncthreads();

    const int myidx = nbrs[base * KNBR + lane];
    const uint4* pn4 = (const uint4*)(PN8 + ((size_t)m * NOTHER + myidx) * DDIM);
    const __half2* psb = s_psb[wid];

    __half2 a2 = __floats2half2_rn(0.f, 0.f);
#pragma unroll
    for (int j = 0; j < 4; j++) {
        uint4 u = pn4[j];
        const int pb = j * 8;
#define PW(word, pi) { \
        __half2 plo = f8x2h2(word); \
        __half2 phi = f8x2h2((word) >> 16); \
        a2 = __hfma2(tanh2(__hadd2(psb[pi], plo)),     s_x[pi],     a2); \
        a2 = __hfma2(tanh2(__hadd2(psb[(pi)+1], phi)), s_x[(pi)+1], a2); }
        PW(u.x, pb); PW(u.y, pb + 2); PW(u.z, pb + 4); PW(u.w, pb + 6);
#undef PW
    }
    float sc = __low2float(a2) + __high2float(a2);

    // softmax over the full axis (lane holds score for its own k)
    const float baseline = (m == 0) ? -1e-9f : 1.220703125e-4f;  // 1/8192
    float mx = sc;
    mx = fmaxf(mx, __shfl_xor_sync(0xffffffffu, mx, 16));
    mx = fmaxf(mx, __shfl_xor_sync(0xffffffffu, mx, 8));
    mx = fmaxf(mx, __shfl_xor_sync(0xffffffffu, mx, 4));
    mx = fmaxf(mx, __shfl_xor_sync(0xffffffffu, mx, 2));
    mx = fmaxf(mx, __shfl_xor_sync(0xffffffffu, mx, 1));
    mx = fmaxf(mx, baseline);

    float e = __expf(sc - mx);
    float s = e;
    s += __shfl_xor_sync(0xffffffffu, s, 16);
    s += __shfl_xor_sync(0xffffffffu, s, 8);
    s += __shfl_xor_sync(0xffffffffu, s, 4);
    s += __shfl_xor_sync(0xffffffffu, s, 2);
    s += __shfl_xor_sync(0xffffffffu, s, 1);
    const float denom = s + (float)(NOTHER - KNBR) * __expf(baseline - mx);
    const float a = e / denom;   // lane k holds A_k

    // aggregation: lanes split the 128 dims (4 each), broadcast a/idx per k
    const float4* src4 = (const float4*)src;
    float4 acc = src4[(size_t)n * 32 + lane];
#pragma unroll
    for (int k = 0; k < KNBR; k++) {
        float ak = __shfl_sync(0xffffffffu, a, k);
        int idx  = __shfl_sync(0xffffffffu, myidx, k);
        unsigned u = ((const unsigned*)(oth8 + (size_t)idx * EDIM))[lane];
        float2 f01 = __half22float2(f8x2h2(u));
        float2 f23 = __half22float2(f8x2h2(u >> 16));
        acc.x += ak * f01.x;
        acc.y += ak * f01.y;
        acc.z += ak * f23.x;
        acc.w += ak * f23.y;
    }
    ((float4*)H)[base * 32 + lane] = acc;
    {
        __nv_bfloat162 lo = __floats2bfloat162_rn(acc.x, acc.y);
        __nv_bfloat162 hi = __floats2bfloat162_rn(acc.z, acc.w);
        uint2 u;
        u.x = *reinterpret_cast<unsigned*>(&lo);
        u.y = *reinterpret_cast<unsigned*>(&hi);
        ((uint2*)Hh)[base * 32 + lane] = u;
    }
}

// ---------------------------------------------------------------------------
// combine: beta = softmax_m(mean partials), out[n,e] = sum_m beta[m]*H[m,n,e].
// Optionally writes an fp8 shadow of out (for next phase's gathers).
// ---------------------------------------------------------------------------
__global__ void __launch_bounds__(256) combine_k(
    const float* __restrict__ H, const float* __restrict__ part, int nblk,
    float* __restrict__ out, unsigned char* __restrict__ outq)
{
    __shared__ float sp[MPATH * 128];
    __shared__ float raws[MPATH];
    __shared__ float sb[MPATH];
    const int tid = threadIdx.x;
    const int wid = tid >> 5;
    const int lane = tid & 31;
    for (int j = tid; j < MPATH * 128; j += 256) sp[j] = part[j];
    __syncthreads();
    if (wid < MPATH) {
        float s = 0.f;
        for (int j = lane; j < nblk; j += 32) s += sp[wid * 128 + j];
        s += __shfl_xor_sync(0xffffffffu, s, 16);
        s += __shfl_xor_sync(0xffffffffu, s, 8);
        s += __shfl_xor_sync(0xffffffffu, s, 4);
        s += __shfl_xor_sync(0xffffffffu, s, 2);
        s += __shfl_xor_sync(0xffffffffu, s, 1);
        if (lane == 0) raws[wid] = s * (1.f / (float)NROW);
    }
    __syncthreads();
    if (tid == 0) {
        float mx = fmaxf(fmaxf(raws[0], raws[1]), fmaxf(raws[2], raws[3]));
        float e0 = expf(raws[0] - mx), e1 = expf(raws[1] - mx);
        float e2 = expf(raws[2] - mx), e3 = expf(raws[3] - mx);
        float dn = e0 + e1 + e2 + e3;
        sb[0] = e0 / dn; sb[1] = e1 / dn; sb[2] = e2 / dn; sb[3] = e3 / dn;
    }
    __syncthreads();

    const int i = blockIdx.x * 256 + tid;
    const int S = NROW * EDIM / 4;
    const float b0 = sb[0], b1 = sb[1], b2 = sb[2], b3 = sb[3];
    const float4* H4 = (const float4*)H;
    float4 h0 = H4[i], h1 = H4[i + S], h2 = H4[i + 2 * S], h3 = H4[i + 3 * S];
    float4 r;
    r.x = b0 * h0.x + b1 * h1.x + b2 * h2.x + b3 * h3.x;
    r.y = b0 * h0.y + b1 * h1.y + b2 * h2.y + b3 * h3.y;
    r.z = b0 * h0.z + b1 * h1.z + b2 * h2.z + b3 * h3.z;
    r.w = b0 * h0.w + b1 * h1.w + b2 * h2.w + b3 * h3.w;
    ((float4*)out)[i] = r;
    if (outq) {
        unsigned u = f2f8(r.x, r.y) | (f2f8(r.z, r.w) << 16);
        ((unsigned*)outq)[i] = u;
    }
}

// fp32 -> fp8 shadow copy
__global__ void tofp8_k(const float* __restrict__ in, unsigned char* __restrict__ out)
{
    const int i = blockIdx.x * 256 + threadIdx.x;
    float4 v = ((const float4*)in)[i];
    unsigned u = f2f8(v.x, v.y) | (f2f8(v.z, v.w) << 16);
    ((unsigned*)out)[i] = u;
}

extern "C" void kernel_launch(void* const* d_in, const int* in_sizes, int n_in,
                              void* d_out, int out_size)
{
    (void)in_sizes; (void)n_in; (void)out_size;

    const float* user    = (const float*)d_in[0];
    const float* product = (const float*)d_in[1];
    const float* V   = (const float*)d_in[2];
    const float* X   = (const float*)d_in[3];
    const float* Wp  = (const float*)d_in[4];
    const float* Bp  = (const float*)d_in[5];
    const float* Wq  = (const float*)d_in[6];
    const float* Bq  = (const float*)d_in[7];
    const float* Q   = (const float*)d_in[8];
    const int* unbrs = (const int*)d_in[9];
    const int* pnbrs = (const int*)d_in[10];
    float* out = (float*)d_out;

    float *dH, *dPart;
    __half* dPSh;
    __nv_bfloat16* dHh;
    unsigned char *dPN8, *dOth8;
    cudaGetSymbolAddress((void**)&dPSh,  g_PSh);
    cudaGetSymbolAddress((void**)&dPN8,  g_PN8);
    cudaGetSymbolAddress((void**)&dOth8, g_oth8);
    cudaGetSymbolAddress((void**)&dH,    g_H);
    cudaGetSymbolAddress((void**)&dHh,   g_Hh);
    cudaGetSymbolAddress((void**)&dPart, g_part);

    cudaFuncSetAttribute(gemm_tc<0>, cudaFuncAttributeMaxDynamicSharedMemorySize, SMEM_BYTES);
    cudaFuncSetAttribute(gemm_tc<1>, cudaFuncAttributeMaxDynamicSharedMemorySize, SMEM_BYTES);

    // fp8 shadow of product for phase-0 gathers
    tofp8_k<<<NOTHER * EDIM / 4 / 256, 256>>>(product, dOth8);

    for (int p = 0; p < 2; p++) {
        const float* src   = (p == 0) ? user    : product;
        const float* other = (p == 0) ? product : out;       // phase 2 attends over user_out
        const int*   nbrs  = (p == 0) ? unbrs   : pnbrs;
        const float* Vp  = V  + (size_t)p * MPATH * EDIM * DDIM;
        const float* Xp  = X  + (size_t)p * MPATH * DDIM;
        const float* Wpp = Wp + (size_t)p * MPATH * EDIM * DDIM;
        const float* Bpp = Bp + (size_t)p * MPATH * DDIM;
        const float* Wqp = Wq + (size_t)p * MPATH * EDIM * DDIM;
        const float* Bqp = Bq + (size_t)p * MPATH * DDIM;
        const float* Qp  = Q  + (size_t)p * MPATH * DDIM;
        float* outp = out + (size_t)p * NROW * EDIM;

        // PSh = fp16(src@V + Bp) (z=0) and PN8 = fp8(other@W_p) (z=1) in ONE launch
        gemm_tc<0><<<dim3(NROW / 64, MPATH, 2), 256, SMEM_BYTES>>>(
            src, Vp, dPSh, other, Wpp, dPN8, nullptr, nullptr, Bpp, nullptr, 0);
        attn_k<<<MPATH * NROW / 8, 256>>>(dPSh, dPN8, Xp, src, dOth8, nbrs, dH, dHh);
        gemm_tc<1><<<dim3(NROW / 64, MPATH, 1), 256, SMEM_BYTES>>>(
            nullptr, Wqp, nullptr, nullptr, nullptr, nullptr, dHh, dPart, Bqp, Qp, 1);
        combine_k<<<NROW * EDIM / 4 / 256, 256>>>(
            dH, dPart, NROW / 64, outp, (p == 0) ? dOth8 : nullptr);
    }
}